// round 11
// baseline (speedup 1.0000x reference)
#include <cuda_runtime.h>
#include <math.h>

// ---------------- problem constants ----------------
#define BATCH 4
#define DD 28
#define HH 28
#define WW 8
#define SP (DD*HH*WW)        // 6272
#define NSP (BATCH*SP)       // 25088 = 196*128
#define CMAX 128
#define PSTRIDE 256

typedef unsigned long long ull;

// ---------------- packed f32x2 helpers ----------------
__device__ __forceinline__ ull pk(float a, float b) {
    ull r; asm("mov.b64 %0,{%1,%2};" : "=l"(r) : "f"(a), "f"(b)); return r;
}
__device__ __forceinline__ void upk(ull v, float& a, float& b) {
    asm("mov.b64 {%0,%1},%2;" : "=f"(a), "=f"(b) : "l"(v));
}
__device__ __forceinline__ ull ff2(ull a, ull b, ull c) {
    ull d; asm("fma.rn.f32x2 %0,%1,%2,%3;" : "=l"(d) : "l"(a), "l"(b), "l"(c)); return d;
}

// ---------------- scratch (static device, no allocs) ----------------
__device__ float g_bufA[BATCH*SP*CMAX];   // activations channel-last [b][sp][c]
__device__ float g_bufB[BATCH*SP*CMAX];
__device__ float2 g_wpair[1000000];       // all transposed weights, duplicated pairs
__device__ float g_ps[784*PSTRIDE];       // BN partial sums (deterministic)
__device__ float g_pq[784*PSTRIDE];
__device__ float2 g_bn[4][CMAX];          // per-layer (scale, shift)

// weight region offsets (in float2 elements)
#define W1_OFF 0                         // 27*1*32   = 864
#define W2_OFF 864                       // 27*32*64  = 55296
#define W3_OFF 56160                     // 27*64*128 = 221184
#define W4_OFF 277344                    // 27*128*81 = 279936
#define W5_OFF 557280                    // 27*128*128= 442368  (end 999648)

#define S1 864
#define S2 55296
#define S3 221184
#define S4 279936
#define S5 442368
#define WT_TOTAL (S1+S2+S3+S4+S5)

// ---------------- merged weight transpose: (O,CIN,27) -> pairs [n][ci][o] ----------------
__global__ void wtrans_all_kernel(const float* __restrict__ w1, const float* __restrict__ w2,
                                  const float* __restrict__ w3, const float* __restrict__ w4,
                                  const float* __restrict__ w5) {
    int idx = blockIdx.x * blockDim.x + threadIdx.x;
    if (idx >= WT_TOTAL) return;
    const float* src; float2* dst; int CIN, COUT; int l = idx;
    if (l < S1)              { src = w1; dst = g_wpair + W1_OFF; CIN = 1;   COUT = 32; }
    else if ((l -= S1) < S2) { src = w2; dst = g_wpair + W2_OFF; CIN = 32;  COUT = 64; }
    else if ((l -= S2) < S3) { src = w3; dst = g_wpair + W3_OFF; CIN = 64;  COUT = 128; }
    else if ((l -= S3) < S4) { src = w4; dst = g_wpair + W4_OFF; CIN = 128; COUT = 81; }
    else { l -= S4; src = w5; dst = g_wpair + W5_OFF; CIN = 128; COUT = 128; }
    int n = l % 27;
    int c = (l / 27) % CIN;
    int o = l / (27 * CIN);
    float v = src[l];
    dst[((size_t)n * CIN + c) * COUT + o] = make_float2(v, v);
}

// ---------------- tiled conv3d, channel-last, f32x2 inner, hoisted weights ----------------
template<int CIN, int COUT, int GROUPS, int BLOCKT, bool RELU, bool NCDHW_OUT, int BN_LAYER, bool STATS>
__global__ void conv_cl_kernel(const float* __restrict__ x, const float2* __restrict__ wp,
                               const float* __restrict__ bias, float* __restrict__ y) {
    constexpr int CH = (CIN < 16) ? CIN : 16;
    constexpr int NCH = CIN / CH;
    constexpr int PH = 4 / GROUPS;           // h-rows per thread
    __shared__ float xs[CH][18][12];   // [ci][zd*6+zh][zw padded 10->12]

    int tid = threadIdx.x;
    int blk = blockIdx.x;
    int hb = blk % 7;
    int d  = (blk / 7) % DD;
    int b  = blk / (7 * DD);
    int h0 = hb * 4;
    int grp = tid / COUT;
    if (grp > GROUPS - 1) grp = GROUPS - 1;
    int o = tid - grp * COUT;
    if (o >= COUT) o = 0;

    ull acc2[PH][4];
    #pragma unroll
    for (int ph = 0; ph < PH; ph++)
        #pragma unroll
        for (int j = 0; j < 4; j++) acc2[ph][j] = 0ull;

    for (int cc = 0; cc < NCH; cc++) {
        __syncthreads();
        // stage input tile (zero-padded halo), coalesced over ci
        for (int i = tid; i < 180 * CH; i += BLOCKT) {
            int ci, pos;
            if (CH == 16) { ci = i & 15; pos = i >> 4; }
            else          { ci = i % CH; pos = i / CH; }
            int zw = pos % 10;
            int zh = (pos / 10) % 6;
            int zd = pos / 60;
            int gd = d + zd - 1, gh = h0 + zh - 1, gw = zw - 1;
            float v = 0.0f;
            int cg = cc * CH + ci;
            if ((unsigned)gd < DD && (unsigned)gh < HH && (unsigned)gw < WW) {
                v = x[((size_t)((b * DD + gd) * HH + gh) * WW + gw) * CIN + cg];
                if (BN_LAYER >= 0) { float2 t = g_bn[BN_LAYER][cg]; v = fmaf(v, t.x, t.y); }
            }
            xs[ci][zd * 6 + zh][zw] = v;
        }
        __syncthreads();

        for (int ci = 0; ci < CH; ci++) {
            int cglob = cc * CH + ci;
            #pragma unroll
            for (int zd = 0; zd < 3; zd++) {
                ull wreg[9];
                #pragma unroll
                for (int t = 0; t < 9; t++)
                    wreg[t] = *(const ull*)&wp[((size_t)(zd * 9 + t) * CIN + cglob) * COUT + o];
                #pragma unroll
                for (int zl = 0; zl < PH + 2; zl++) {
                    const float2* row = (const float2*)&xs[ci][zd * 6 + grp * PH + zl][0];
                    float2 e0 = row[0], e1 = row[1], e2 = row[2], e3 = row[3], e4 = row[4];
                    ull P[9];
                    P[0] = pk(e0.x, e0.y); P[2] = pk(e1.x, e1.y); P[4] = pk(e2.x, e2.y);
                    P[6] = pk(e3.x, e3.y); P[8] = pk(e4.x, e4.y);
                    P[1] = pk(e0.y, e1.x); P[3] = pk(e1.y, e2.x);
                    P[5] = pk(e2.y, e3.x); P[7] = pk(e3.y, e4.x);
                    #pragma unroll
                    for (int ph = 0; ph < PH; ph++) {
                        int kh1 = zl - ph;               // kh+1
                        if (kh1 < 0 || kh1 > 2) continue; // constant-folds
                        #pragma unroll
                        for (int kw1 = 0; kw1 < 3; kw1++) {
                            ull wv2 = wreg[kh1 * 3 + kw1];
                            #pragma unroll
                            for (int j = 0; j < 4; j++)
                                acc2[ph][j] = ff2(wv2, P[kw1 + 2 * j], acc2[ph][j]);
                        }
                    }
                }
            }
        }
    }

    if (tid < GROUPS * COUT) {
        float bs = bias[o];
        float ssum = 0.f, sq = 0.f;
        #pragma unroll
        for (int ph = 0; ph < PH; ph++) {
            int h = h0 + grp * PH + ph;
            #pragma unroll
            for (int j = 0; j < 4; j++) {
                float v0, v1; upk(acc2[ph][j], v0, v1);
                v0 += bs; v1 += bs;
                if (RELU) { v0 = fmaxf(v0, 0.f); v1 = fmaxf(v1, 0.f); }
                if (STATS) { ssum += v0 + v1; sq += v0 * v0 + v1 * v1; }
                int pw = 2 * j;
                if (NCDHW_OUT) {
                    size_t base = (size_t)(b * COUT + o) * SP + (size_t)(d * HH + h) * WW;
                    y[base + pw] = v0; y[base + pw + 1] = v1;
                } else {
                    size_t base = ((size_t)((b * DD + d) * HH + h) * WW + pw) * COUT + o;
                    y[base] = v0; y[base + COUT] = v1;
                }
            }
        }
        if (STATS) { g_ps[blk * PSTRIDE + tid] = ssum; g_pq[blk * PSTRIDE + tid] = sq; }
    }
}

// ---------------- BN finalize: reduce per-block partials -> (scale, shift) ----------------
// grid = C blocks; partial layout: g_ps[i*PSTRIDE + g*C + c]
__global__ void bn_fin_kernel(const float* __restrict__ gma, const float* __restrict__ bta,
                              int layer, int nblk, int groups, int C) {
    int c = blockIdx.x;
    int t = threadIdx.x;
    __shared__ float sh0[256], sh1[256];
    float s = 0.f, q = 0.f;
    for (int i = t; i < nblk; i += 256) {
        for (int g = 0; g < groups; g++) {
            s += g_ps[i * PSTRIDE + g * C + c];
            q += g_pq[i * PSTRIDE + g * C + c];
        }
    }
    sh0[t] = s; sh1[t] = q;
    __syncthreads();
    for (int st = 128; st > 0; st >>= 1) {
        if (t < st) { sh0[t] += sh0[t + st]; sh1[t] += sh1[t + st]; }
        __syncthreads();
    }
    if (t == 0) {
        float m = sh0[0] / (float)NSP;
        float var = sh1[0] / (float)NSP - m * m;
        float r = rsqrtf(var + 1e-5f);
        float sc = r * gma[c];
        g_bn[layer][c] = make_float2(sc, bta[c] - m * sc);
    }
}

// in-place BN apply (only needed for layer 3, consumed by offset conv + deform)
__global__ void bn_apply_kernel(float* __restrict__ y, int layer, int C) {
    int idx = blockIdx.x * blockDim.x + threadIdx.x;
    if (idx >= NSP * C) return;
    int c = idx % C;
    float2 t = g_bn[layer][c];
    y[idx] = fmaf(y[idx], t.x, t.y);
}

// ---------------- deformable conv: 32-pos tile, 256 threads (2 position-halves) ----------------
__global__ void __launch_bounds__(256) deform_kernel(const float* __restrict__ ht,
                                                     const float* __restrict__ off,
                                                     const float2* __restrict__ wp,
                                                     const float* __restrict__ db,
                                                     float* __restrict__ y) {
    __shared__ float s_tile[128 * 36];     // [c][p], row stride 36 floats (144B, 16B-aligned)
    __shared__ int   s_qd[32], s_qh[32], s_qw[32];
    __shared__ float s_td[32], s_th[32], s_tw[32];

    int tid = threadIdx.x;
    int c_ = tid & 127;        // channel (sampling) / output channel (GEMV)
    int half = tid >> 7;       // which 16 of the 32 positions
    int posBase = blockIdx.x * 32;

    ull acc2[8];
    #pragma unroll
    for (int j = 0; j < 8; j++) acc2[j] = 0ull;

    for (int n = 0; n < 27; n++) {
        int kd = n / 9 - 1, kh = (n / 3) % 3 - 1, kw = n % 3 - 1;
        __syncthreads();
        if (tid < 32) {
            int s = posBase + tid;
            int w = s & 7;
            int t = s >> 3;
            int h = t % HH; t /= HH;
            int d = t % DD;
            int b = t / DD;
            size_t obase = (size_t)b * 81 * SP + (size_t)((d * HH + h) * WW + w);
            float od  = off[obase + (size_t)n * SP];
            float oh  = off[obase + (size_t)(27 + n) * SP];
            float ow_ = off[obase + (size_t)(54 + n) * SP];
            float pd = fminf(fmaxf((float)(d + 1 + kd) + od, 0.f), 29.f);
            float ph = fminf(fmaxf((float)(h + 1 + kh) + oh, 0.f), 29.f);
            float pw = fminf(fmaxf((float)(w + 1 + kw) + ow_, 0.f), 9.f);
            float fd = fminf(fmaxf(floorf(pd), 0.f), 28.f);
            float fh = fminf(fmaxf(floorf(ph), 0.f), 28.f);
            float fw = fminf(fmaxf(floorf(pw), 0.f), 8.f);
            s_qd[tid] = (int)fd; s_td[tid] = fminf(fmaxf(pd - fd, 0.f), 1.f);
            s_qh[tid] = (int)fh; s_th[tid] = fminf(fmaxf(ph - fh, 0.f), 1.f);
            s_qw[tid] = (int)fw; s_tw[tid] = fminf(fmaxf(pw - fw, 0.f), 1.f);
        }
        __syncthreads();

        // sampling: thread = (channel, half), 16 positions each
        for (int pl = 0; pl < 16; pl++) {
            int p = half * 16 + pl;
            int s = posBase + p;
            int b = s / SP;
            int qd = s_qd[p], qh = s_qh[p], qw = s_qw[p];
            float td = s_td[p], th = s_th[p], tw = s_tw[p];
            float v = 0.f;
            #pragma unroll
            for (int i = 0; i < 2; i++) {
                int zd = qd + i - 1;
                if ((unsigned)zd >= DD) continue;
                float gd = i ? td : (1.f - td);
                #pragma unroll
                for (int j = 0; j < 2; j++) {
                    int zh = qh + j - 1;
                    if ((unsigned)zh >= HH) continue;
                    float gdh = gd * (j ? th : (1.f - th));
                    #pragma unroll
                    for (int k = 0; k < 2; k++) {
                        int zw = qw + k - 1;
                        if ((unsigned)zw >= WW) continue;
                        float g = gdh * (k ? tw : (1.f - tw));
                        size_t base = (size_t)((b * DD + zd) * HH + zh) * WW + zw;
                        v += g * ht[base * CMAX + c_];
                    }
                }
            }
            s_tile[c_ * 36 + p] = v;
        }
        __syncthreads();

        // GEMV: thread = (output channel, half); 128-bit broadcast smem reads
        const float2* wrow = wp + (size_t)n * 128 * 128;
        for (int c = 0; c < 128; c++) {
            ull wv2 = *(const ull*)&wrow[c * 128 + c_];
            const ulonglong2* st2 = (const ulonglong2*)(s_tile + c * 36 + half * 16);
            #pragma unroll
            for (int k = 0; k < 4; k++) {
                ulonglong2 q = st2[k];
                acc2[2 * k]     = ff2(wv2, q.x, acc2[2 * k]);
                acc2[2 * k + 1] = ff2(wv2, q.y, acc2[2 * k + 1]);
            }
        }
    }

    float bs = db[c_];
    float ssum = 0.f, sq = 0.f;
    #pragma unroll
    for (int j = 0; j < 8; j++) {
        float v0, v1; upk(acc2[j], v0, v1);
        v0 = fmaxf(v0 + bs, 0.f); v1 = fmaxf(v1 + bs, 0.f);
        ssum += v0 + v1; sq += v0 * v0 + v1 * v1;
        int s0 = posBase + half * 16 + 2 * j;
        y[(size_t)s0 * CMAX + c_]       = v0;
        y[(size_t)(s0 + 1) * CMAX + c_] = v1;
    }
    g_ps[blockIdx.x * PSTRIDE + half * 128 + c_] = ssum;
    g_pq[blockIdx.x * PSTRIDE + half * 128 + c_] = sq;
}

// ---------------- global avg pool (+BN4) + FC + log_softmax ----------------
__global__ void head_kernel(const float* __restrict__ y, const float* __restrict__ fcw,
                            const float* __restrict__ fcb, float* __restrict__ out) {
    int b = blockIdx.x;
    int c = threadIdx.x;   // 128
    const float* p = y + (size_t)b * SP * CMAX + c;
    float s = 0.f;
    for (int i = 0; i < SP; i++) s += p[(size_t)i * CMAX];
    __shared__ float pooled[128];
    __shared__ float logits[10];
    float2 bn = g_bn[3][c];
    pooled[c] = fmaf(s / (float)SP, bn.x, bn.y);
    __syncthreads();
    if (c < 10) {
        float l = fcb[c];
        for (int k = 0; k < 128; k++) l += pooled[k] * fcw[c * 128 + k];
        logits[c] = l;
    }
    __syncthreads();
    if (c == 0) {
        float mx = logits[0];
        for (int j = 1; j < 10; j++) mx = fmaxf(mx, logits[j]);
        float se = 0.f;
        for (int j = 0; j < 10; j++) se += expf(logits[j] - mx);
        float lse = mx + logf(se);
        for (int j = 0; j < 10; j++) out[b * 10 + j] = logits[j] - lse;
    }
}

// ---------------- launcher ----------------
extern "C" void kernel_launch(void* const* d_in, const int* in_sizes, int n_in,
                              void* d_out, int out_size) {
    const float* x   = (const float*)d_in[0];
    const float* c1w = (const float*)d_in[1];  const float* c1b = (const float*)d_in[2];
    const float* g1  = (const float*)d_in[3];  const float* b1  = (const float*)d_in[4];
    const float* c2w = (const float*)d_in[5];  const float* c2b = (const float*)d_in[6];
    const float* g2  = (const float*)d_in[7];  const float* b2  = (const float*)d_in[8];
    const float* c3w = (const float*)d_in[9];  const float* c3b = (const float*)d_in[10];
    const float* g3  = (const float*)d_in[11]; const float* b3  = (const float*)d_in[12];
    const float* ow  = (const float*)d_in[13]; const float* ob  = (const float*)d_in[14];
    const float* dw  = (const float*)d_in[15]; const float* db  = (const float*)d_in[16];
    const float* g4  = (const float*)d_in[17]; const float* b4  = (const float*)d_in[18];
    const float* fcw = (const float*)d_in[19]; const float* fcb = (const float*)d_in[20];

    float* out = (float*)d_out;
    float* offsets = out + BATCH * 10;   // logits first, then offsets (NCDHW)

    float *bufA, *bufB; float2* wpair;
    cudaGetSymbolAddress((void**)&bufA, g_bufA);
    cudaGetSymbolAddress((void**)&bufB, g_bufB);
    cudaGetSymbolAddress((void**)&wpair, g_wpair);

    auto grid = [](int total) { return (total + 255) / 256; };

    wtrans_all_kernel<<<(WT_TOTAL + 255) / 256, 256>>>(c1w, c2w, c3w, ow, dw);

    const int CBLK = BATCH * DD * (HH / 4);   // 784

    // layer 1: conv(1->32)+relu, stats fused (BN0 applied in conv2 staging)
    conv_cl_kernel<1, 32, 4, 128, true, false, -1, true><<<CBLK, 128>>>(x, wpair + W1_OFF, c1b, bufA);
    bn_fin_kernel<<<32, 256>>>(g1, b1, 0, CBLK, 4, 32);

    // layer 2: conv(32->64)+relu (applies BN0), stats fused
    conv_cl_kernel<32, 64, 2, 128, true, false, 0, true><<<CBLK, 128>>>(bufA, wpair + W2_OFF, c2b, bufB);
    bn_fin_kernel<<<64, 256>>>(g2, b2, 1, CBLK, 2, 64);

    // layer 3: conv(64->128)+relu (applies BN1), stats fused, explicit BN2 apply
    conv_cl_kernel<64, 128, 1, 128, true, false, 1, true><<<CBLK, 128>>>(bufB, wpair + W3_OFF, c3b, bufA);
    bn_fin_kernel<<<128, 256>>>(g3, b3, 2, CBLK, 1, 128);
    bn_apply_kernel<<<grid(NSP*128), 256>>>(bufA, 2, 128);

    // offsets conv (128->81), input already BN'd, NCDHW into output buffer (96 threads)
    conv_cl_kernel<128, 81, 1, 96, false, true, -1, false><<<CBLK, 96>>>(bufA, wpair + W4_OFF, ob, offsets);

    // deformable conv (128->128) + relu, 256 threads, stats fused (BN3 folded into head)
    deform_kernel<<<NSP / 32, 256>>>(bufA, offsets, wpair + W5_OFF, db, bufB);
    bn_fin_kernel<<<128, 256>>>(g4, b4, 3, NSP / 32, 2, 128);

    // pool (+BN3 affine) + fc + log_softmax
    head_kernel<<<BATCH, 128>>>(bufB, fcw, fcb, out);
}

// round 12
// speedup vs baseline: 1.0524x; 1.0524x over previous
#include <cuda_runtime.h>
#include <math.h>

// ---------------- problem constants ----------------
#define BATCH 4
#define DD 28
#define HH 28
#define WW 8
#define SP (DD*HH*WW)        // 6272
#define NSP (BATCH*SP)       // 25088 = 196*128
#define CMAX 128

typedef unsigned long long ull;

// ---------------- packed f32x2 helpers ----------------
__device__ __forceinline__ ull pk(float a, float b) {
    ull r; asm("mov.b64 %0,{%1,%2};" : "=l"(r) : "f"(a), "f"(b)); return r;
}
__device__ __forceinline__ void upk(ull v, float& a, float& b) {
    asm("mov.b64 {%0,%1},%2;" : "=f"(a), "=f"(b) : "l"(v));
}
__device__ __forceinline__ ull ff2(ull a, ull b, ull c) {
    ull d; asm("fma.rn.f32x2 %0,%1,%2,%3;" : "=l"(d) : "l"(a), "l"(b), "l"(c)); return d;
}

// ---------------- scratch (static device, no allocs) ----------------
__device__ float g_bufA[BATCH*SP*CMAX];   // activations channel-last [b][sp][c]
__device__ float g_bufB[BATCH*SP*CMAX];
__device__ float g_bufC[BATCH*SP*CMAX];   // deform partial (n 0..13)
__device__ float g_bufD[BATCH*SP*CMAX];   // deform partial (n 14..26)
__device__ float2 g_wpair[1000000];       // all transposed weights, duplicated pairs
__device__ float g_ps[784*CMAX];          // BN partial sums (deterministic)
__device__ float g_pq[784*CMAX];
__device__ float2 g_bn[4][CMAX];          // per-layer (scale, shift)

// weight region offsets (in float2 elements)
#define W1_OFF 0                         // 27*1*32   = 864
#define W2_OFF 864                       // 27*32*64  = 55296
#define W3_OFF 56160                     // 27*64*128 = 221184
#define W4_OFF 277344                    // 27*128*81 = 279936
#define W5_OFF 557280                    // 27*128*128= 442368  (end 999648)

#define S1 864
#define S2 55296
#define S3 221184
#define S4 279936
#define S5 442368
#define WT_TOTAL (S1+S2+S3+S4+S5)

// ---------------- merged weight transpose: (O,CIN,27) -> pairs [n][ci][o] ----------------
__global__ void wtrans_all_kernel(const float* __restrict__ w1, const float* __restrict__ w2,
                                  const float* __restrict__ w3, const float* __restrict__ w4,
                                  const float* __restrict__ w5) {
    int idx = blockIdx.x * blockDim.x + threadIdx.x;
    if (idx >= WT_TOTAL) return;
    const float* src; float2* dst; int CIN, COUT; int l = idx;
    if (l < S1)              { src = w1; dst = g_wpair + W1_OFF; CIN = 1;   COUT = 32; }
    else if ((l -= S1) < S2) { src = w2; dst = g_wpair + W2_OFF; CIN = 32;  COUT = 64; }
    else if ((l -= S2) < S3) { src = w3; dst = g_wpair + W3_OFF; CIN = 64;  COUT = 128; }
    else if ((l -= S3) < S4) { src = w4; dst = g_wpair + W4_OFF; CIN = 128; COUT = 81; }
    else { l -= S4; src = w5; dst = g_wpair + W5_OFF; CIN = 128; COUT = 128; }
    int n = l % 27;
    int c = (l / 27) % CIN;
    int o = l / (27 * CIN);
    float v = src[l];
    dst[((size_t)n * CIN + c) * COUT + o] = make_float2(v, v);
}

// ---------------- tiled conv3d, channel-last, f32x2 inner, hoisted weights ----------------
template<int CIN, int COUT, int GROUPS, int BLOCKT, bool RELU, bool NCDHW_OUT, int BN_LAYER, bool STATS>
__global__ void conv_cl_kernel(const float* __restrict__ x, const float2* __restrict__ wp,
                               const float* __restrict__ bias, float* __restrict__ y) {
    constexpr int CH = (CIN < 16) ? CIN : 16;
    constexpr int NCH = CIN / CH;
    constexpr int PH = 4 / GROUPS;           // h-rows per thread
    __shared__ float xs[CH][18][12];   // [ci][zd*6+zh][zw padded 10->12]

    int tid = threadIdx.x;
    int blk = blockIdx.x;
    int hb = blk % 7;
    int d  = (blk / 7) % DD;
    int b  = blk / (7 * DD);
    int h0 = hb * 4;
    int grp = tid / COUT;
    if (grp > GROUPS - 1) grp = GROUPS - 1;
    int o = tid - grp * COUT;
    if (o >= COUT) o = 0;

    ull acc2[PH][4];
    #pragma unroll
    for (int ph = 0; ph < PH; ph++)
        #pragma unroll
        for (int j = 0; j < 4; j++) acc2[ph][j] = 0ull;

    for (int cc = 0; cc < NCH; cc++) {
        __syncthreads();
        // stage input tile (zero-padded halo), coalesced over ci
        for (int i = tid; i < 180 * CH; i += BLOCKT) {
            int ci, pos;
            if (CH == 16) { ci = i & 15; pos = i >> 4; }
            else          { ci = i % CH; pos = i / CH; }
            int zw = pos % 10;
            int zh = (pos / 10) % 6;
            int zd = pos / 60;
            int gd = d + zd - 1, gh = h0 + zh - 1, gw = zw - 1;
            float v = 0.0f;
            int cg = cc * CH + ci;
            if ((unsigned)gd < DD && (unsigned)gh < HH && (unsigned)gw < WW) {
                v = x[((size_t)((b * DD + gd) * HH + gh) * WW + gw) * CIN + cg];
                if (BN_LAYER >= 0) { float2 t = g_bn[BN_LAYER][cg]; v = fmaf(v, t.x, t.y); }
            }
            xs[ci][zd * 6 + zh][zw] = v;
        }
        __syncthreads();

        for (int ci = 0; ci < CH; ci++) {
            int cglob = cc * CH + ci;
            #pragma unroll
            for (int zd = 0; zd < 3; zd++) {
                ull wreg[9];
                #pragma unroll
                for (int t = 0; t < 9; t++)
                    wreg[t] = *(const ull*)&wp[((size_t)(zd * 9 + t) * CIN + cglob) * COUT + o];
                #pragma unroll
                for (int zl = 0; zl < PH + 2; zl++) {
                    const float2* row = (const float2*)&xs[ci][zd * 6 + grp * PH + zl][0];
                    float2 e0 = row[0], e1 = row[1], e2 = row[2], e3 = row[3], e4 = row[4];
                    ull P[9];
                    P[0] = pk(e0.x, e0.y); P[2] = pk(e1.x, e1.y); P[4] = pk(e2.x, e2.y);
                    P[6] = pk(e3.x, e3.y); P[8] = pk(e4.x, e4.y);
                    P[1] = pk(e0.y, e1.x); P[3] = pk(e1.y, e2.x);
                    P[5] = pk(e2.y, e3.x); P[7] = pk(e3.y, e4.x);
                    #pragma unroll
                    for (int ph = 0; ph < PH; ph++) {
                        int kh1 = zl - ph;               // kh+1
                        if (kh1 < 0 || kh1 > 2) continue; // constant-folds
                        #pragma unroll
                        for (int kw1 = 0; kw1 < 3; kw1++) {
                            ull wv2 = wreg[kh1 * 3 + kw1];
                            #pragma unroll
                            for (int j = 0; j < 4; j++)
                                acc2[ph][j] = ff2(wv2, P[kw1 + 2 * j], acc2[ph][j]);
                        }
                    }
                }
            }
        }
    }

    if (tid < GROUPS * COUT) {
        float bs = bias[o];
        float ssum = 0.f, sq = 0.f;
        #pragma unroll
        for (int ph = 0; ph < PH; ph++) {
            int h = h0 + grp * PH + ph;
            #pragma unroll
            for (int j = 0; j < 4; j++) {
                float v0, v1; upk(acc2[ph][j], v0, v1);
                v0 += bs; v1 += bs;
                if (RELU) { v0 = fmaxf(v0, 0.f); v1 = fmaxf(v1, 0.f); }
                if (STATS) { ssum += v0 + v1; sq += v0 * v0 + v1 * v1; }
                int pw = 2 * j;
                if (NCDHW_OUT) {
                    size_t base = (size_t)(b * COUT + o) * SP + (size_t)(d * HH + h) * WW;
                    y[base + pw] = v0; y[base + pw + 1] = v1;
                } else {
                    size_t base = ((size_t)((b * DD + d) * HH + h) * WW + pw) * COUT + o;
                    y[base] = v0; y[base + COUT] = v1;
                }
            }
        }
        if (STATS) { g_ps[blk * CMAX + tid] = ssum; g_pq[blk * CMAX + tid] = sq; }
    }
}

// ---------------- BN finalize: reduce per-block partials -> (scale, shift) ----------------
__global__ void bn_fin_kernel(const float* __restrict__ gma, const float* __restrict__ bta,
                              int layer, int nblk, int groups, int C) {
    int c = blockIdx.x;
    int t = threadIdx.x;
    __shared__ float sh0[256], sh1[256];
    float s = 0.f, q = 0.f;
    for (int i = t; i < nblk; i += 256) {
        for (int g = 0; g < groups; g++) {
            s += g_ps[i * CMAX + g * C + c];
            q += g_pq[i * CMAX + g * C + c];
        }
    }
    sh0[t] = s; sh1[t] = q;
    __syncthreads();
    for (int st = 128; st > 0; st >>= 1) {
        if (t < st) { sh0[t] += sh0[t + st]; sh1[t] += sh1[t + st]; }
        __syncthreads();
    }
    if (t == 0) {
        float m = sh0[0] / (float)NSP;
        float var = sh1[0] / (float)NSP - m * m;
        float r = rsqrtf(var + 1e-5f);
        float sc = r * gma[c];
        g_bn[layer][c] = make_float2(sc, bta[c] - m * sc);
    }
}

// in-place BN apply (only needed for layer 3, consumed by offset conv + deform)
__global__ void bn_apply_kernel(float* __restrict__ y, int layer, int C) {
    int idx = blockIdx.x * blockDim.x + threadIdx.x;
    if (idx >= NSP * C) return;
    int c = idx % C;
    float2 t = g_bn[layer][c];
    y[idx] = fmaf(y[idx], t.x, t.y);
}

// ---------------- deformable conv partial: taps [nStart, nStart+nCount) ----------------
// 128 threads, 32-pos tile (measured-best shape); writes raw partial sums (no bias/relu).
__global__ void deform_kernel(const float* __restrict__ ht,   // channel-last h3 [pos][128]
                              const float* __restrict__ off,  // (B,81,D,H,W) NCDHW
                              const float2* __restrict__ wp,  // [n][c][o] duplicated pairs
                              float* __restrict__ y,          // partial out, channel-last
                              int nStart, int nCount) {
    __shared__ float s_tile[128 * 36];     // [c][p], row stride 36 floats (144B, 16B-aligned)
    __shared__ int   s_qd[32], s_qh[32], s_qw[32];
    __shared__ float s_td[32], s_th[32], s_tw[32];

    int tid = threadIdx.x;
    int posBase = blockIdx.x * 32;

    ull acc2[16];
    #pragma unroll
    for (int j = 0; j < 16; j++) acc2[j] = 0ull;

    for (int nn = 0; nn < nCount; nn++) {
        int n = nStart + nn;
        int kd = n / 9 - 1, kh = (n / 3) % 3 - 1, kw = n % 3 - 1;
        __syncthreads();
        if (tid < 32) {
            int s = posBase + tid;
            int w = s & 7;
            int t = s >> 3;
            int h = t % HH; t /= HH;
            int d = t % DD;
            int b = t / DD;
            size_t obase = (size_t)b * 81 * SP + (size_t)((d * HH + h) * WW + w);
            float od  = off[obase + (size_t)n * SP];
            float oh  = off[obase + (size_t)(27 + n) * SP];
            float ow_ = off[obase + (size_t)(54 + n) * SP];
            float pd = fminf(fmaxf((float)(d + 1 + kd) + od, 0.f), 29.f);
            float ph = fminf(fmaxf((float)(h + 1 + kh) + oh, 0.f), 29.f);
            float pw = fminf(fmaxf((float)(w + 1 + kw) + ow_, 0.f), 9.f);
            float fd = fminf(fmaxf(floorf(pd), 0.f), 28.f);
            float fh = fminf(fmaxf(floorf(ph), 0.f), 28.f);
            float fw = fminf(fmaxf(floorf(pw), 0.f), 8.f);
            s_qd[tid] = (int)fd; s_td[tid] = fminf(fmaxf(pd - fd, 0.f), 1.f);
            s_qh[tid] = (int)fh; s_th[tid] = fminf(fmaxf(ph - fh, 0.f), 1.f);
            s_qw[tid] = (int)fw; s_tw[tid] = fminf(fmaxf(pw - fw, 0.f), 1.f);
        }
        __syncthreads();

        // sampling: thread = channel, loop positions
        for (int p = 0; p < 32; p++) {
            int s = posBase + p;
            int b = s / SP;
            int qd = s_qd[p], qh = s_qh[p], qw = s_qw[p];
            float td = s_td[p], th = s_th[p], tw = s_tw[p];
            float v = 0.f;
            #pragma unroll
            for (int i = 0; i < 2; i++) {
                int zd = qd + i - 1;
                if ((unsigned)zd >= DD) continue;
                float gd = i ? td : (1.f - td);
                #pragma unroll
                for (int j = 0; j < 2; j++) {
                    int zh = qh + j - 1;
                    if ((unsigned)zh >= HH) continue;
                    float gdh = gd * (j ? th : (1.f - th));
                    #pragma unroll
                    for (int k = 0; k < 2; k++) {
                        int zw = qw + k - 1;
                        if ((unsigned)zw >= WW) continue;
                        float g = gdh * (k ? tw : (1.f - tw));
                        size_t base = (size_t)((b * DD + zd) * HH + zh) * WW + zw;
                        v += g * ht[base * CMAX + tid];
                    }
                }
            }
            s_tile[tid * 36 + p] = v;
        }
        __syncthreads();

        // GEMV: thread = output channel; 128-bit broadcast smem reads
        const float2* wrow = wp + (size_t)n * 128 * 128;
        for (int c = 0; c < 128; c++) {
            ull wv2 = *(const ull*)&wrow[c * 128 + tid];
            const ulonglong2* st2 = (const ulonglong2*)(s_tile + c * 36);
            #pragma unroll
            for (int k = 0; k < 8; k++) {
                ulonglong2 q = st2[k];
                acc2[2 * k]     = ff2(wv2, q.x, acc2[2 * k]);
                acc2[2 * k + 1] = ff2(wv2, q.y, acc2[2 * k + 1]);
            }
        }
    }

    #pragma unroll
    for (int j = 0; j < 16; j++) {
        float v0, v1; upk(acc2[j], v0, v1);
        int s0 = posBase + 2 * j;
        y[(size_t)s0 * CMAX + tid]       = v0;
        y[(size_t)(s0 + 1) * CMAX + tid] = v1;
    }
}

// ---------------- combine partials: bias + relu + stats ----------------
__global__ void deform_combine_kernel(const float* __restrict__ p1, const float* __restrict__ p2,
                                      const float* __restrict__ db, float* __restrict__ y) {
    int blk = blockIdx.x;        // 196 position chunks of 128
    int c = threadIdx.x;         // 128
    float bs = db[c];
    float ssum = 0.f, sq = 0.f;
    int base = blk * 128;
    for (int i = 0; i < 128; i++) {
        size_t idx = (size_t)(base + i) * CMAX + c;
        float v = fmaxf(p1[idx] + p2[idx] + bs, 0.f);
        y[idx] = v;
        ssum += v; sq += v * v;
    }
    g_ps[blk * CMAX + c] = ssum;
    g_pq[blk * CMAX + c] = sq;
}

// ---------------- global avg pool (+BN4) + FC + log_softmax ----------------
__global__ void head_kernel(const float* __restrict__ y, const float* __restrict__ fcw,
                            const float* __restrict__ fcb, float* __restrict__ out) {
    int b = blockIdx.x;
    int c = threadIdx.x;   // 128
    const float* p = y + (size_t)b * SP * CMAX + c;
    float s = 0.f;
    for (int i = 0; i < SP; i++) s += p[(size_t)i * CMAX];
    __shared__ float pooled[128];
    __shared__ float logits[10];
    float2 bn = g_bn[3][c];
    pooled[c] = fmaf(s / (float)SP, bn.x, bn.y);
    __syncthreads();
    if (c < 10) {
        float l = fcb[c];
        for (int k = 0; k < 128; k++) l += pooled[k] * fcw[c * 128 + k];
        logits[c] = l;
    }
    __syncthreads();
    if (c == 0) {
        float mx = logits[0];
        for (int j = 1; j < 10; j++) mx = fmaxf(mx, logits[j]);
        float se = 0.f;
        for (int j = 0; j < 10; j++) se += expf(logits[j] - mx);
        float lse = mx + logf(se);
        for (int j = 0; j < 10; j++) out[b * 10 + j] = logits[j] - lse;
    }
}

// ---------------- launcher ----------------
extern "C" void kernel_launch(void* const* d_in, const int* in_sizes, int n_in,
                              void* d_out, int out_size) {
    const float* x   = (const float*)d_in[0];
    const float* c1w = (const float*)d_in[1];  const float* c1b = (const float*)d_in[2];
    const float* g1  = (const float*)d_in[3];  const float* b1  = (const float*)d_in[4];
    const float* c2w = (const float*)d_in[5];  const float* c2b = (const float*)d_in[6];
    const float* g2  = (const float*)d_in[7];  const float* b2  = (const float*)d_in[8];
    const float* c3w = (const float*)d_in[9];  const float* c3b = (const float*)d_in[10];
    const float* g3  = (const float*)d_in[11]; const float* b3  = (const float*)d_in[12];
    const float* ow  = (const float*)d_in[13]; const float* ob  = (const float*)d_in[14];
    const float* dw  = (const float*)d_in[15]; const float* db  = (const float*)d_in[16];
    const float* g4  = (const float*)d_in[17]; const float* b4  = (const float*)d_in[18];
    const float* fcw = (const float*)d_in[19]; const float* fcb = (const float*)d_in[20];

    float* out = (float*)d_out;
    float* offsets = out + BATCH * 10;   // logits first, then offsets (NCDHW)

    float *bufA, *bufB, *bufC, *bufD; float2* wpair;
    cudaGetSymbolAddress((void**)&bufA, g_bufA);
    cudaGetSymbolAddress((void**)&bufB, g_bufB);
    cudaGetSymbolAddress((void**)&bufC, g_bufC);
    cudaGetSymbolAddress((void**)&bufD, g_bufD);
    cudaGetSymbolAddress((void**)&wpair, g_wpair);

    auto grid = [](int total) { return (total + 255) / 256; };

    wtrans_all_kernel<<<(WT_TOTAL + 255) / 256, 256>>>(c1w, c2w, c3w, ow, dw);

    const int CBLK = BATCH * DD * (HH / 4);   // 784

    // layer 1: conv(1->32)+relu, stats fused (BN0 applied in conv2 staging)
    conv_cl_kernel<1, 32, 4, 128, true, false, -1, true><<<CBLK, 128>>>(x, wpair + W1_OFF, c1b, bufA);
    bn_fin_kernel<<<32, 256>>>(g1, b1, 0, CBLK, 4, 32);

    // layer 2: conv(32->64)+relu (applies BN0), stats fused
    conv_cl_kernel<32, 64, 2, 128, true, false, 0, true><<<CBLK, 128>>>(bufA, wpair + W2_OFF, c2b, bufB);
    bn_fin_kernel<<<64, 256>>>(g2, b2, 1, CBLK, 2, 64);

    // layer 3: conv(64->128)+relu (applies BN1), stats fused, explicit BN2 apply
    conv_cl_kernel<64, 128, 1, 128, true, false, 1, true><<<CBLK, 128>>>(bufB, wpair + W3_OFF, c3b, bufA);
    bn_fin_kernel<<<128, 256>>>(g3, b3, 2, CBLK, 1, 128);
    bn_apply_kernel<<<grid(NSP*128), 256>>>(bufA, 2, 128);

    // offsets conv (128->81), input already BN'd, NCDHW into output buffer (96 threads)
    conv_cl_kernel<128, 81, 1, 96, false, true, -1, false><<<CBLK, 96>>>(bufA, wpair + W4_OFF, ob, offsets);

    // deformable conv split over taps: two independent partial kernels, then combine
    deform_kernel<<<NSP / 32, 128>>>(bufA, offsets, wpair + W5_OFF, bufC, 0, 14);
    deform_kernel<<<NSP / 32, 128>>>(bufA, offsets, wpair + W5_OFF, bufD, 14, 13);
    deform_combine_kernel<<<196, 128>>>(bufC, bufD, db, bufB);
    bn_fin_kernel<<<128, 256>>>(g4, b4, 3, 196, 1, 128);

    // pool (+BN3 affine) + fc + log_softmax
    head_kernel<<<BATCH, 128>>>(bufB, fcw, fcb, out);
}

// round 13
// speedup vs baseline: 1.0560x; 1.0034x over previous
#include <cuda_runtime.h>
#include <math.h>

// ---------------- problem constants ----------------
#define BATCH 4
#define DD 28
#define HH 28
#define WW 8
#define SP (DD*HH*WW)        // 6272
#define NSP (BATCH*SP)       // 25088 = 196*128
#define CMAX 128

typedef unsigned long long ull;

// ---------------- packed f32x2 helpers ----------------
__device__ __forceinline__ ull pk(float a, float b) {
    ull r; asm("mov.b64 %0,{%1,%2};" : "=l"(r) : "f"(a), "f"(b)); return r;
}
__device__ __forceinline__ void upk(ull v, float& a, float& b) {
    asm("mov.b64 {%0,%1},%2;" : "=f"(a), "=f"(b) : "l"(v));
}
__device__ __forceinline__ ull ff2(ull a, ull b, ull c) {
    ull d; asm("fma.rn.f32x2 %0,%1,%2,%3;" : "=l"(d) : "l"(a), "l"(b), "l"(c)); return d;
}

// ---------------- scratch (static device, no allocs) ----------------
__device__ float g_bufA[BATCH*SP*CMAX];   // activations channel-last [b][sp][c]
__device__ float g_bufB[BATCH*SP*CMAX];
__device__ float2 g_wpair[1000000];       // all transposed weights, duplicated pairs
__device__ float g_ps[1568*CMAX];         // BN partial sums (deterministic)
__device__ float g_pq[1568*CMAX];
__device__ float2 g_bn[4][CMAX];          // per-layer (scale, shift)

// weight region offsets (in float2 elements)
#define W1_OFF 0                         // 27*1*32   = 864
#define W2_OFF 864                       // 27*32*64  = 55296
#define W3_OFF 56160                     // 27*64*128 = 221184
#define W4_OFF 277344                    // 27*128*81 = 279936
#define W5_OFF 557280                    // 27*128*128= 442368  (end 999648)

#define S1 864
#define S2 55296
#define S3 221184
#define S4 279936
#define S5 442368
#define WT_TOTAL (S1+S2+S3+S4+S5)

// ---------------- merged weight transpose: (O,CIN,27) -> pairs [n][ci][o] ----------------
__global__ void wtrans_all_kernel(const float* __restrict__ w1, const float* __restrict__ w2,
                                  const float* __restrict__ w3, const float* __restrict__ w4,
                                  const float* __restrict__ w5) {
    int idx = blockIdx.x * blockDim.x + threadIdx.x;
    if (idx >= WT_TOTAL) return;
    const float* src; float2* dst; int CIN, COUT; int l = idx;
    if (l < S1)              { src = w1; dst = g_wpair + W1_OFF; CIN = 1;   COUT = 32; }
    else if ((l -= S1) < S2) { src = w2; dst = g_wpair + W2_OFF; CIN = 32;  COUT = 64; }
    else if ((l -= S2) < S3) { src = w3; dst = g_wpair + W3_OFF; CIN = 64;  COUT = 128; }
    else if ((l -= S3) < S4) { src = w4; dst = g_wpair + W4_OFF; CIN = 128; COUT = 81; }
    else { l -= S4; src = w5; dst = g_wpair + W5_OFF; CIN = 128; COUT = 128; }
    int n = l % 27;
    int c = (l / 27) % CIN;
    int o = l / (27 * CIN);
    float v = src[l];
    dst[((size_t)n * CIN + c) * COUT + o] = make_float2(v, v);
}

// ---------------- tiled conv3d, channel-last, f32x2 inner, hoisted weights ----------------
// TH = tile height (h-rows per block); grid = B*D*(H/TH). PH = TH/GROUPS rows/thread.
template<int CIN, int COUT, int TH, int GROUPS, int BLOCKT,
         bool RELU, bool NCDHW_OUT, int BN_LAYER, bool STATS>
__global__ void conv_cl_kernel(const float* __restrict__ x, const float2* __restrict__ wp,
                               const float* __restrict__ bias, float* __restrict__ y) {
    constexpr int CH = (CIN < 16) ? CIN : 16;
    constexpr int NCH = CIN / CH;
    constexpr int PH = TH / GROUPS;          // h-rows per thread
    constexpr int ZH = TH + 2;               // staged rows per zd-plane
    constexpr int HB = HH / TH;              // h-tiles
    __shared__ float xs[CH][3 * ZH][12];     // [ci][zd*ZH+zh][zw padded 10->12]

    int tid = threadIdx.x;
    int blk = blockIdx.x;
    int hb = blk % HB;
    int d  = (blk / HB) % DD;
    int b  = blk / (HB * DD);
    int h0 = hb * TH;
    int grp = tid / COUT;
    if (grp > GROUPS - 1) grp = GROUPS - 1;
    int o = tid - grp * COUT;
    if (o >= COUT) o = 0;

    ull acc2[PH][4];
    #pragma unroll
    for (int ph = 0; ph < PH; ph++)
        #pragma unroll
        for (int j = 0; j < 4; j++) acc2[ph][j] = 0ull;

    for (int cc = 0; cc < NCH; cc++) {
        __syncthreads();
        // stage input tile (zero-padded halo), coalesced over ci
        for (int i = tid; i < 30 * ZH * CH; i += BLOCKT) {
            int ci, pos;
            if (CH == 16) { ci = i & 15; pos = i >> 4; }
            else          { ci = i % CH; pos = i / CH; }
            int zw = pos % 10;
            int zh = (pos / 10) % ZH;
            int zd = pos / (10 * ZH);
            int gd = d + zd - 1, gh = h0 + zh - 1, gw = zw - 1;
            float v = 0.0f;
            int cg = cc * CH + ci;
            if ((unsigned)gd < DD && (unsigned)gh < HH && (unsigned)gw < WW) {
                v = x[((size_t)((b * DD + gd) * HH + gh) * WW + gw) * CIN + cg];
                if (BN_LAYER >= 0) { float2 t = g_bn[BN_LAYER][cg]; v = fmaf(v, t.x, t.y); }
            }
            xs[ci][zd * ZH + zh][zw] = v;
        }
        __syncthreads();

        for (int ci = 0; ci < CH; ci++) {
            int cglob = cc * CH + ci;
            #pragma unroll
            for (int zd = 0; zd < 3; zd++) {
                // hoist the 9 taps of this zd-plane into registers (one LDG each)
                ull wreg[9];
                #pragma unroll
                for (int t = 0; t < 9; t++)
                    wreg[t] = *(const ull*)&wp[((size_t)(zd * 9 + t) * CIN + cglob) * COUT + o];
                #pragma unroll
                for (int zl = 0; zl < PH + 2; zl++) {
                    const float2* row = (const float2*)&xs[ci][zd * ZH + grp * PH + zl][0];
                    float2 e0 = row[0], e1 = row[1], e2 = row[2], e3 = row[3], e4 = row[4];
                    ull P[9];
                    P[0] = pk(e0.x, e0.y); P[2] = pk(e1.x, e1.y); P[4] = pk(e2.x, e2.y);
                    P[6] = pk(e3.x, e3.y); P[8] = pk(e4.x, e4.y);
                    P[1] = pk(e0.y, e1.x); P[3] = pk(e1.y, e2.x);
                    P[5] = pk(e2.y, e3.x); P[7] = pk(e3.y, e4.x);
                    #pragma unroll
                    for (int ph = 0; ph < PH; ph++) {
                        int kh1 = zl - ph;               // kh+1
                        if (kh1 < 0 || kh1 > 2) continue; // constant-folds
                        #pragma unroll
                        for (int kw1 = 0; kw1 < 3; kw1++) {
                            ull wv2 = wreg[kh1 * 3 + kw1];
                            #pragma unroll
                            for (int j = 0; j < 4; j++)
                                acc2[ph][j] = ff2(wv2, P[kw1 + 2 * j], acc2[ph][j]);
                        }
                    }
                }
            }
        }
    }

    if (tid < GROUPS * COUT) {
        float bs = bias[o];
        float ssum = 0.f, sq = 0.f;
        #pragma unroll
        for (int ph = 0; ph < PH; ph++) {
            int h = h0 + grp * PH + ph;
            #pragma unroll
            for (int j = 0; j < 4; j++) {
                float v0, v1; upk(acc2[ph][j], v0, v1);
                v0 += bs; v1 += bs;
                if (RELU) { v0 = fmaxf(v0, 0.f); v1 = fmaxf(v1, 0.f); }
                if (STATS) { ssum += v0 + v1; sq += v0 * v0 + v1 * v1; }
                int pw = 2 * j;
                if (NCDHW_OUT) {
                    size_t base = (size_t)(b * COUT + o) * SP + (size_t)(d * HH + h) * WW;
                    y[base + pw] = v0; y[base + pw + 1] = v1;
                } else {
                    size_t base = ((size_t)((b * DD + d) * HH + h) * WW + pw) * COUT + o;
                    y[base] = v0; y[base + COUT] = v1;
                }
            }
        }
        if (STATS) { g_ps[blk * CMAX + tid] = ssum; g_pq[blk * CMAX + tid] = sq; }
    }
}

// ---------------- BN finalize: reduce per-block partials -> (scale, shift) ----------------
__global__ void bn_fin_kernel(const float* __restrict__ gma, const float* __restrict__ bta,
                              int layer, int nblk, int groups, int C) {
    int c = blockIdx.x;
    int t = threadIdx.x;
    __shared__ float sh0[256], sh1[256];
    float s = 0.f, q = 0.f;
    for (int i = t; i < nblk; i += 256) {
        for (int g = 0; g < groups; g++) {
            s += g_ps[i * CMAX + g * C + c];
            q += g_pq[i * CMAX + g * C + c];
        }
    }
    sh0[t] = s; sh1[t] = q;
    __syncthreads();
    for (int st = 128; st > 0; st >>= 1) {
        if (t < st) { sh0[t] += sh0[t + st]; sh1[t] += sh1[t + st]; }
        __syncthreads();
    }
    if (t == 0) {
        float m = sh0[0] / (float)NSP;
        float var = sh1[0] / (float)NSP - m * m;
        float r = rsqrtf(var + 1e-5f);
        float sc = r * gma[c];
        g_bn[layer][c] = make_float2(sc, bta[c] - m * sc);
    }
}

// in-place BN apply (only needed for layer 3, consumed by offset conv + deform)
__global__ void bn_apply_kernel(float* __restrict__ y, int layer, int C) {
    int idx = blockIdx.x * blockDim.x + threadIdx.x;
    if (idx >= NSP * C) return;
    int c = idx % C;
    float2 t = g_bn[layer][c];
    y[idx] = fmaf(y[idx], t.x, t.y);
}

// ---------------- deformable conv (measured-best 32-pos shape) + fused stats ----------------
__global__ void deform_kernel(const float* __restrict__ ht,   // channel-last h3 [pos][128]
                              const float* __restrict__ off,  // (B,81,D,H,W) NCDHW
                              const float2* __restrict__ wp,  // [n][c][o] duplicated pairs
                              const float* __restrict__ db,
                              float* __restrict__ y) {        // channel-last out
    __shared__ float s_tile[128 * 36];     // [c][p], row stride 36 floats (144B, 16B-aligned)
    __shared__ int   s_qd[32], s_qh[32], s_qw[32];
    __shared__ float s_td[32], s_th[32], s_tw[32];

    int tid = threadIdx.x;
    int posBase = blockIdx.x * 32;

    ull acc2[16];
    #pragma unroll
    for (int j = 0; j < 16; j++) acc2[j] = 0ull;

    for (int n = 0; n < 27; n++) {
        int kd = n / 9 - 1, kh = (n / 3) % 3 - 1, kw = n % 3 - 1;
        __syncthreads();
        if (tid < 32) {
            int s = posBase + tid;
            int w = s & 7;
            int t = s >> 3;
            int h = t % HH; t /= HH;
            int d = t % DD;
            int b = t / DD;
            size_t obase = (size_t)b * 81 * SP + (size_t)((d * HH + h) * WW + w);
            float od  = off[obase + (size_t)n * SP];
            float oh  = off[obase + (size_t)(27 + n) * SP];
            float ow_ = off[obase + (size_t)(54 + n) * SP];
            float pd = fminf(fmaxf((float)(d + 1 + kd) + od, 0.f), 29.f);
            float ph = fminf(fmaxf((float)(h + 1 + kh) + oh, 0.f), 29.f);
            float pw = fminf(fmaxf((float)(w + 1 + kw) + ow_, 0.f), 9.f);
            float fd = fminf(fmaxf(floorf(pd), 0.f), 28.f);
            float fh = fminf(fmaxf(floorf(ph), 0.f), 28.f);
            float fw = fminf(fmaxf(floorf(pw), 0.f), 8.f);
            s_qd[tid] = (int)fd; s_td[tid] = fminf(fmaxf(pd - fd, 0.f), 1.f);
            s_qh[tid] = (int)fh; s_th[tid] = fminf(fmaxf(ph - fh, 0.f), 1.f);
            s_qw[tid] = (int)fw; s_tw[tid] = fminf(fmaxf(pw - fw, 0.f), 1.f);
        }
        __syncthreads();

        // sampling: thread = channel, loop positions
        for (int p = 0; p < 32; p++) {
            int s = posBase + p;
            int b = s / SP;
            int qd = s_qd[p], qh = s_qh[p], qw = s_qw[p];
            float td = s_td[p], th = s_th[p], tw = s_tw[p];
            float v = 0.f;
            #pragma unroll
            for (int i = 0; i < 2; i++) {
                int zd = qd + i - 1;
                if ((unsigned)zd >= DD) continue;
                float gd = i ? td : (1.f - td);
                #pragma unroll
                for (int j = 0; j < 2; j++) {
                    int zh = qh + j - 1;
                    if ((unsigned)zh >= HH) continue;
                    float gdh = gd * (j ? th : (1.f - th));
                    #pragma unroll
                    for (int k = 0; k < 2; k++) {
                        int zw = qw + k - 1;
                        if ((unsigned)zw >= WW) continue;
                        float g = gdh * (k ? tw : (1.f - tw));
                        size_t base = (size_t)((b * DD + zd) * HH + zh) * WW + zw;
                        v += g * ht[base * CMAX + tid];
                    }
                }
            }
            s_tile[tid * 36 + p] = v;
        }
        __syncthreads();

        // GEMV: thread = output channel; 128-bit broadcast smem reads
        const float2* wrow = wp + (size_t)n * 128 * 128;
        for (int c = 0; c < 128; c++) {
            ull wv2 = *(const ull*)&wrow[c * 128 + tid];
            const ulonglong2* st2 = (const ulonglong2*)(s_tile + c * 36);
            #pragma unroll
            for (int k = 0; k < 8; k++) {
                ulonglong2 q = st2[k];
                acc2[2 * k]     = ff2(wv2, q.x, acc2[2 * k]);
                acc2[2 * k + 1] = ff2(wv2, q.y, acc2[2 * k + 1]);
            }
        }
    }

    float bs = db[tid];
    float ssum = 0.f, sq = 0.f;
    #pragma unroll
    for (int j = 0; j < 16; j++) {
        float v0, v1; upk(acc2[j], v0, v1);
        v0 = fmaxf(v0 + bs, 0.f); v1 = fmaxf(v1 + bs, 0.f);
        ssum += v0 + v1; sq += v0 * v0 + v1 * v1;
        int s0 = posBase + 2 * j;
        y[(size_t)s0 * CMAX + tid]       = v0;
        y[(size_t)(s0 + 1) * CMAX + tid] = v1;
    }
    g_ps[blockIdx.x * CMAX + tid] = ssum;
    g_pq[blockIdx.x * CMAX + tid] = sq;
}

// ---------------- global avg pool (+BN4) + FC + log_softmax ----------------
__global__ void head_kernel(const float* __restrict__ y, const float* __restrict__ fcw,
                            const float* __restrict__ fcb, float* __restrict__ out) {
    int b = blockIdx.x;
    int c = threadIdx.x;   // 128
    const float* p = y + (size_t)b * SP * CMAX + c;
    float s = 0.f;
    for (int i = 0; i < SP; i++) s += p[(size_t)i * CMAX];
    __shared__ float pooled[128];
    __shared__ float logits[10];
    float2 bn = g_bn[3][c];
    pooled[c] = fmaf(s / (float)SP, bn.x, bn.y);
    __syncthreads();
    if (c < 10) {
        float l = fcb[c];
        for (int k = 0; k < 128; k++) l += pooled[k] * fcw[c * 128 + k];
        logits[c] = l;
    }
    __syncthreads();
    if (c == 0) {
        float mx = logits[0];
        for (int j = 1; j < 10; j++) mx = fmaxf(mx, logits[j]);
        float se = 0.f;
        for (int j = 0; j < 10; j++) se += expf(logits[j] - mx);
        float lse = mx + logf(se);
        for (int j = 0; j < 10; j++) out[b * 10 + j] = logits[j] - lse;
    }
}

// ---------------- launcher ----------------
extern "C" void kernel_launch(void* const* d_in, const int* in_sizes, int n_in,
                              void* d_out, int out_size) {
    const float* x   = (const float*)d_in[0];
    const float* c1w = (const float*)d_in[1];  const float* c1b = (const float*)d_in[2];
    const float* g1  = (const float*)d_in[3];  const float* b1  = (const float*)d_in[4];
    const float* c2w = (const float*)d_in[5];  const float* c2b = (const float*)d_in[6];
    const float* g2  = (const float*)d_in[7];  const float* b2  = (const float*)d_in[8];
    const float* c3w = (const float*)d_in[9];  const float* c3b = (const float*)d_in[10];
    const float* g3  = (const float*)d_in[11]; const float* b3  = (const float*)d_in[12];
    const float* ow  = (const float*)d_in[13]; const float* ob  = (const float*)d_in[14];
    const float* dw  = (const float*)d_in[15]; const float* db  = (const float*)d_in[16];
    const float* g4  = (const float*)d_in[17]; const float* b4  = (const float*)d_in[18];
    const float* fcw = (const float*)d_in[19]; const float* fcb = (const float*)d_in[20];

    float* out = (float*)d_out;
    float* offsets = out + BATCH * 10;   // logits first, then offsets (NCDHW)

    float *bufA, *bufB; float2* wpair;
    cudaGetSymbolAddress((void**)&bufA, g_bufA);
    cudaGetSymbolAddress((void**)&bufB, g_bufB);
    cudaGetSymbolAddress((void**)&wpair, g_wpair);

    auto grid = [](int total) { return (total + 255) / 256; };

    wtrans_all_kernel<<<(WT_TOTAL + 255) / 256, 256>>>(c1w, c2w, c3w, ow, dw);

    const int CBLK4 = BATCH * DD * (HH / 4);   // 784  (TH=4)
    const int CBLK2 = BATCH * DD * (HH / 2);   // 1568 (TH=2)

    // layer 1: conv(1->32)+relu, TH=4 GROUPS=4 (tiny layer, unchanged shape)
    conv_cl_kernel<1, 32, 4, 4, 128, true, false, -1, true><<<CBLK4, 128>>>(x, wpair + W1_OFF, c1b, bufA);
    bn_fin_kernel<<<32, 256>>>(g1, b1, 0, CBLK4, 4, 32);

    // layer 2: conv(32->64)+relu (applies BN0), TH=2 GROUPS=2 -> grid 1568
    conv_cl_kernel<32, 64, 2, 2, 128, true, false, 0, true><<<CBLK2, 128>>>(bufA, wpair + W2_OFF, c2b, bufB);
    bn_fin_kernel<<<64, 256>>>(g2, b2, 1, CBLK2, 2, 64);

    // layer 3: conv(64->128)+relu (applies BN1), TH=2 GROUPS=1 -> grid 1568
    conv_cl_kernel<64, 128, 2, 1, 128, true, false, 1, true><<<CBLK2, 128>>>(bufB, wpair + W3_OFF, c3b, bufA);
    bn_fin_kernel<<<128, 256>>>(g3, b3, 2, CBLK2, 1, 128);
    bn_apply_kernel<<<grid(NSP*128), 256>>>(bufA, 2, 128);

    // offsets conv (128->81), TH=2 GROUPS=1, 96 threads -> grid 1568
    conv_cl_kernel<128, 81, 2, 1, 96, false, true, -1, false><<<CBLK2, 96>>>(bufA, wpair + W4_OFF, ob, offsets);

    // deformable conv (128->128) + relu, stats fused (BN3 folded into head)
    deform_kernel<<<NSP / 32, 128>>>(bufA, offsets, wpair + W5_OFF, db, bufB);
    bn_fin_kernel<<<128, 256>>>(g4, b4, 3, NSP / 32, 1, 128);

    // pool (+BN3 affine) + fc + log_softmax
    head_kernel<<<BATCH, 128>>>(bufB, fcw, fcb, out);
}

// round 14
// speedup vs baseline: 1.1214x; 1.0620x over previous
#include <cuda_runtime.h>
#include <math.h>

// ---------------- problem constants ----------------
#define BATCH 4
#define DD 28
#define HH 28
#define WW 8
#define SP (DD*HH*WW)        // 6272
#define NSP (BATCH*SP)       // 25088 = 196*128
#define CMAX 128

typedef unsigned long long ull;

// ---------------- packed f32x2 helpers ----------------
__device__ __forceinline__ ull pk(float a, float b) {
    ull r; asm("mov.b64 %0,{%1,%2};" : "=l"(r) : "f"(a), "f"(b)); return r;
}
__device__ __forceinline__ void upk(ull v, float& a, float& b) {
    asm("mov.b64 {%0,%1},%2;" : "=f"(a), "=f"(b) : "l"(v));
}
__device__ __forceinline__ ull ff2(ull a, ull b, ull c) {
    ull d; asm("fma.rn.f32x2 %0,%1,%2,%3;" : "=l"(d) : "l"(a), "l"(b), "l"(c)); return d;
}

// ---------------- scratch (static device, no allocs) ----------------
__device__ float g_bufA[BATCH*SP*CMAX];   // activations channel-last [b][sp][c]
__device__ float g_bufB[BATCH*SP*CMAX];
__device__ float2 g_wpair[1000000];       // all transposed weights, duplicated pairs
__device__ float g_ps[784*CMAX];          // BN partial sums (deterministic)
__device__ float g_pq[784*CMAX];
__device__ float2 g_bn[4][CMAX];          // per-layer (scale, shift)

// weight region offsets (in float2 elements)
#define W1_OFF 0                         // 27*1*32   = 864
#define W2_OFF 864                       // 27*32*64  = 55296
#define W3_OFF 56160                     // 27*64*128 = 221184
#define W4_OFF 277344                    // 27*128*81 = 279936
#define W5_OFF 557280                    // 27*128*128= 442368  (end 999648)

#define S1 864
#define S2 55296
#define S3 221184
#define S4 279936
#define S5 442368
#define WT_TOTAL (S1+S2+S3+S4+S5)

// ---------------- merged weight transpose: (O,CIN,27) -> pairs [n][ci][o] ----------------
__global__ void wtrans_all_kernel(const float* __restrict__ w1, const float* __restrict__ w2,
                                  const float* __restrict__ w3, const float* __restrict__ w4,
                                  const float* __restrict__ w5) {
    int idx = blockIdx.x * blockDim.x + threadIdx.x;
    if (idx >= WT_TOTAL) return;
    const float* src; float2* dst; int CIN, COUT; int l = idx;
    if (l < S1)              { src = w1; dst = g_wpair + W1_OFF; CIN = 1;   COUT = 32; }
    else if ((l -= S1) < S2) { src = w2; dst = g_wpair + W2_OFF; CIN = 32;  COUT = 64; }
    else if ((l -= S2) < S3) { src = w3; dst = g_wpair + W3_OFF; CIN = 64;  COUT = 128; }
    else if ((l -= S3) < S4) { src = w4; dst = g_wpair + W4_OFF; CIN = 128; COUT = 81; }
    else { l -= S4; src = w5; dst = g_wpair + W5_OFF; CIN = 128; COUT = 128; }
    int n = l % 27;
    int c = (l / 27) % CIN;
    int o = l / (27 * CIN);
    float v = src[l];
    dst[((size_t)n * CIN + c) * COUT + o] = make_float2(v, v);
}

// ---------------- tiled conv3d, channel-last, f32x2 inner, hoisted weights ----------------
// BLOCKT threads, tile: 4h x 8w at fixed d. grid = B*D*(H/4) = 784
template<int CIN, int COUT, int GROUPS, int BLOCKT, bool RELU, bool NCDHW_OUT, int BN_LAYER, bool STATS>
__global__ void conv_cl_kernel(const float* __restrict__ x, const float2* __restrict__ wp,
                               const float* __restrict__ bias, float* __restrict__ y) {
    constexpr int CH = (CIN < 16) ? CIN : 16;
    constexpr int NCH = CIN / CH;
    constexpr int PH = 4 / GROUPS;           // h-rows per thread
    __shared__ float xs[CH][18][12];   // [ci][zd*6+zh][zw padded 10->12]

    int tid = threadIdx.x;
    int blk = blockIdx.x;
    int hb = blk % 7;
    int d  = (blk / 7) % DD;
    int b  = blk / (7 * DD);
    int h0 = hb * 4;
    int grp = tid / COUT;
    if (grp > GROUPS - 1) grp = GROUPS - 1;
    int o = tid - grp * COUT;
    if (o >= COUT) o = 0;

    ull acc2[PH][4];
    #pragma unroll
    for (int ph = 0; ph < PH; ph++)
        #pragma unroll
        for (int j = 0; j < 4; j++) acc2[ph][j] = 0ull;

    for (int cc = 0; cc < NCH; cc++) {
        __syncthreads();
        // stage input tile (zero-padded halo), coalesced over ci
        for (int i = tid; i < 180 * CH; i += BLOCKT) {
            int ci, pos;
            if (CH == 16) { ci = i & 15; pos = i >> 4; }
            else          { ci = i % CH; pos = i / CH; }
            int zw = pos % 10;
            int zh = (pos / 10) % 6;
            int zd = pos / 60;
            int gd = d + zd - 1, gh = h0 + zh - 1, gw = zw - 1;
            float v = 0.0f;
            int cg = cc * CH + ci;
            if ((unsigned)gd < DD && (unsigned)gh < HH && (unsigned)gw < WW) {
                v = x[((size_t)((b * DD + gd) * HH + gh) * WW + gw) * CIN + cg];
                if (BN_LAYER >= 0) { float2 t = g_bn[BN_LAYER][cg]; v = fmaf(v, t.x, t.y); }
            }
            xs[ci][zd * 6 + zh][zw] = v;
        }
        __syncthreads();

        for (int ci = 0; ci < CH; ci++) {
            int cglob = cc * CH + ci;
            #pragma unroll
            for (int zd = 0; zd < 3; zd++) {
                // hoist the 9 taps of this zd-plane into registers (one LDG each)
                ull wreg[9];
                #pragma unroll
                for (int t = 0; t < 9; t++)
                    wreg[t] = *(const ull*)&wp[((size_t)(zd * 9 + t) * CIN + cglob) * COUT + o];
                #pragma unroll
                for (int zl = 0; zl < PH + 2; zl++) {
                    const float2* row = (const float2*)&xs[ci][zd * 6 + grp * PH + zl][0];
                    float2 e0 = row[0], e1 = row[1], e2 = row[2], e3 = row[3], e4 = row[4];
                    ull P[9];
                    P[0] = pk(e0.x, e0.y); P[2] = pk(e1.x, e1.y); P[4] = pk(e2.x, e2.y);
                    P[6] = pk(e3.x, e3.y); P[8] = pk(e4.x, e4.y);
                    P[1] = pk(e0.y, e1.x); P[3] = pk(e1.y, e2.x);
                    P[5] = pk(e2.y, e3.x); P[7] = pk(e3.y, e4.x);
                    #pragma unroll
                    for (int ph = 0; ph < PH; ph++) {
                        int kh1 = zl - ph;               // kh+1
                        if (kh1 < 0 || kh1 > 2) continue; // constant-folds
                        #pragma unroll
                        for (int kw1 = 0; kw1 < 3; kw1++) {
                            ull wv2 = wreg[kh1 * 3 + kw1];
                            #pragma unroll
                            for (int j = 0; j < 4; j++)
                                acc2[ph][j] = ff2(wv2, P[kw1 + 2 * j], acc2[ph][j]);
                        }
                    }
                }
            }
        }
    }

    if (tid < GROUPS * COUT) {
        float bs = bias[o];
        float ssum = 0.f, sq = 0.f;
        #pragma unroll
        for (int ph = 0; ph < PH; ph++) {
            int h = h0 + grp * PH + ph;
            #pragma unroll
            for (int j = 0; j < 4; j++) {
                float v0, v1; upk(acc2[ph][j], v0, v1);
                v0 += bs; v1 += bs;
                if (RELU) { v0 = fmaxf(v0, 0.f); v1 = fmaxf(v1, 0.f); }
                if (STATS) { ssum += v0 + v1; sq += v0 * v0 + v1 * v1; }
                int pw = 2 * j;
                if (NCDHW_OUT) {
                    size_t base = (size_t)(b * COUT + o) * SP + (size_t)(d * HH + h) * WW;
                    y[base + pw] = v0; y[base + pw + 1] = v1;
                } else {
                    size_t base = ((size_t)((b * DD + d) * HH + h) * WW + pw) * COUT + o;
                    y[base] = v0; y[base + COUT] = v1;
                }
            }
        }
        if (STATS) { g_ps[blk * CMAX + tid] = ssum; g_pq[blk * CMAX + tid] = sq; }
    }
}

// ---------------- BN finalize: reduce per-block partials -> (scale, shift) ----------------
__global__ void bn_fin_kernel(const float* __restrict__ gma, const float* __restrict__ bta,
                              int layer, int nblk, int groups, int C) {
    int c = blockIdx.x;
    int t = threadIdx.x;
    __shared__ float sh0[256], sh1[256];
    float s = 0.f, q = 0.f;
    for (int i = t; i < nblk; i += 256) {
        for (int g = 0; g < groups; g++) {
            s += g_ps[i * CMAX + g * C + c];
            q += g_pq[i * CMAX + g * C + c];
        }
    }
    sh0[t] = s; sh1[t] = q;
    __syncthreads();
    for (int st = 128; st > 0; st >>= 1) {
        if (t < st) { sh0[t] += sh0[t + st]; sh1[t] += sh1[t + st]; }
        __syncthreads();
    }
    if (t == 0) {
        float m = sh0[0] / (float)NSP;
        float var = sh1[0] / (float)NSP - m * m;
        float r = rsqrtf(var + 1e-5f);
        float sc = r * gma[c];
        g_bn[layer][c] = make_float2(sc, bta[c] - m * sc);
    }
}

// in-place BN apply (only needed for layer 3, consumed by offset conv + deform)
__global__ void bn_apply_kernel(float* __restrict__ y, int layer, int C) {
    int idx = blockIdx.x * blockDim.x + threadIdx.x;
    if (idx >= NSP * C) return;
    int c = idx % C;
    float2 t = g_bn[layer][c];
    y[idx] = fmaf(y[idx], t.x, t.y);
}

// ---------------- deformable conv: output NOT stored, only per-block channel sums ----------------
// The post-BN4 deform output feeds ONLY the global average pool, so the tensor itself
// is dead — per-block (32-position) channel sums + sum-of-squares are sufficient.
__global__ void deform_kernel(const float* __restrict__ ht,   // channel-last h3 [pos][128]
                              const float* __restrict__ off,  // (B,81,D,H,W) NCDHW
                              const float2* __restrict__ wp,  // [n][c][o] duplicated pairs
                              const float* __restrict__ db) {
    __shared__ float s_tile[128 * 36];     // [c][p], row stride 36 floats (144B, 16B-aligned)
    __shared__ int   s_qd[32], s_qh[32], s_qw[32];
    __shared__ float s_td[32], s_th[32], s_tw[32];

    int tid = threadIdx.x;
    int posBase = blockIdx.x * 32;

    ull acc2[16];
    #pragma unroll
    for (int j = 0; j < 16; j++) acc2[j] = 0ull;

    for (int n = 0; n < 27; n++) {
        int kd = n / 9 - 1, kh = (n / 3) % 3 - 1, kw = n % 3 - 1;
        __syncthreads();
        if (tid < 32) {
            int s = posBase + tid;
            int w = s & 7;
            int t = s >> 3;
            int h = t % HH; t /= HH;
            int d = t % DD;
            int b = t / DD;
            size_t obase = (size_t)b * 81 * SP + (size_t)((d * HH + h) * WW + w);
            float od  = off[obase + (size_t)n * SP];
            float oh  = off[obase + (size_t)(27 + n) * SP];
            float ow_ = off[obase + (size_t)(54 + n) * SP];
            float pd = fminf(fmaxf((float)(d + 1 + kd) + od, 0.f), 29.f);
            float ph = fminf(fmaxf((float)(h + 1 + kh) + oh, 0.f), 29.f);
            float pw = fminf(fmaxf((float)(w + 1 + kw) + ow_, 0.f), 9.f);
            float fd = fminf(fmaxf(floorf(pd), 0.f), 28.f);
            float fh = fminf(fmaxf(floorf(ph), 0.f), 28.f);
            float fw = fminf(fmaxf(floorf(pw), 0.f), 8.f);
            s_qd[tid] = (int)fd; s_td[tid] = fminf(fmaxf(pd - fd, 0.f), 1.f);
            s_qh[tid] = (int)fh; s_th[tid] = fminf(fmaxf(ph - fh, 0.f), 1.f);
            s_qw[tid] = (int)fw; s_tw[tid] = fminf(fmaxf(pw - fw, 0.f), 1.f);
        }
        __syncthreads();

        // sampling: thread = channel, loop positions
        for (int p = 0; p < 32; p++) {
            int s = posBase + p;
            int b = s / SP;
            int qd = s_qd[p], qh = s_qh[p], qw = s_qw[p];
            float td = s_td[p], th = s_th[p], tw = s_tw[p];
            float v = 0.f;
            #pragma unroll
            for (int i = 0; i < 2; i++) {
                int zd = qd + i - 1;
                if ((unsigned)zd >= DD) continue;
                float gd = i ? td : (1.f - td);
                #pragma unroll
                for (int j = 0; j < 2; j++) {
                    int zh = qh + j - 1;
                    if ((unsigned)zh >= HH) continue;
                    float gdh = gd * (j ? th : (1.f - th));
                    #pragma unroll
                    for (int k = 0; k < 2; k++) {
                        int zw = qw + k - 1;
                        if ((unsigned)zw >= WW) continue;
                        float g = gdh * (k ? tw : (1.f - tw));
                        size_t base = (size_t)((b * DD + zd) * HH + zh) * WW + zw;
                        v += g * ht[base * CMAX + tid];
                    }
                }
            }
            s_tile[tid * 36 + p] = v;
        }
        __syncthreads();

        // GEMV: thread = output channel; 128-bit broadcast smem reads
        const float2* wrow = wp + (size_t)n * 128 * 128;
        for (int c = 0; c < 128; c++) {
            ull wv2 = *(const ull*)&wrow[c * 128 + tid];
            const ulonglong2* st2 = (const ulonglong2*)(s_tile + c * 36);
            #pragma unroll
            for (int k = 0; k < 8; k++) {
                ulonglong2 q = st2[k];
                acc2[2 * k]     = ff2(wv2, q.x, acc2[2 * k]);
                acc2[2 * k + 1] = ff2(wv2, q.y, acc2[2 * k + 1]);
            }
        }
    }

    float bs = db[tid];
    float ssum = 0.f, sq = 0.f;
    #pragma unroll
    for (int j = 0; j < 16; j++) {
        float v0, v1; upk(acc2[j], v0, v1);
        v0 = fmaxf(v0 + bs, 0.f); v1 = fmaxf(v1 + bs, 0.f);
        ssum += v0 + v1; sq += v0 * v0 + v1 * v1;
    }
    g_ps[blockIdx.x * CMAX + tid] = ssum;
    g_pq[blockIdx.x * CMAX + tid] = sq;
}

// ---------------- head: pool from deform per-block partials (+BN4) + FC + log_softmax ----------------
// Blocks of 32 positions never straddle batches (SP % 32 == 0): batch b owns blocks
// [b*196, (b+1)*196). pooled[b][c] = (sum of g_ps over those blocks) / SP.
__global__ void head_kernel(const float* __restrict__ fcw, const float* __restrict__ fcb,
                            float* __restrict__ out) {
    int b = blockIdx.x;
    int c = threadIdx.x;   // 128
    float s = 0.f;
    const float* pp = g_ps + (size_t)(b * 196) * CMAX + c;
    for (int i = 0; i < 196; i++) s += pp[(size_t)i * CMAX];
    __shared__ float pooled[128];
    __shared__ float logits[10];
    float2 bn = g_bn[3][c];
    pooled[c] = fmaf(s / (float)SP, bn.x, bn.y);
    __syncthreads();
    if (c < 10) {
        float l = fcb[c];
        for (int k = 0; k < 128; k++) l += pooled[k] * fcw[c * 128 + k];
        logits[c] = l;
    }
    __syncthreads();
    if (c == 0) {
        float mx = logits[0];
        for (int j = 1; j < 10; j++) mx = fmaxf(mx, logits[j]);
        float se = 0.f;
        for (int j = 0; j < 10; j++) se += expf(logits[j] - mx);
        float lse = mx + logf(se);
        for (int j = 0; j < 10; j++) out[b * 10 + j] = logits[j] - lse;
    }
}

// ---------------- launcher ----------------
extern "C" void kernel_launch(void* const* d_in, const int* in_sizes, int n_in,
                              void* d_out, int out_size) {
    const float* x   = (const float*)d_in[0];
    const float* c1w = (const float*)d_in[1];  const float* c1b = (const float*)d_in[2];
    const float* g1  = (const float*)d_in[3];  const float* b1  = (const float*)d_in[4];
    const float* c2w = (const float*)d_in[5];  const float* c2b = (const float*)d_in[6];
    const float* g2  = (const float*)d_in[7];  const float* b2  = (const float*)d_in[8];
    const float* c3w = (const float*)d_in[9];  const float* c3b = (const float*)d_in[10];
    const float* g3  = (const float*)d_in[11]; const float* b3  = (const float*)d_in[12];
    const float* ow  = (const float*)d_in[13]; const float* ob  = (const float*)d_in[14];
    const float* dw  = (const float*)d_in[15]; const float* db  = (const float*)d_in[16];
    const float* g4  = (const float*)d_in[17]; const float* b4  = (const float*)d_in[18];
    const float* fcw = (const float*)d_in[19]; const float* fcb = (const float*)d_in[20];

    float* out = (float*)d_out;
    float* offsets = out + BATCH * 10;   // logits first, then offsets (NCDHW)

    float *bufA, *bufB; float2* wpair;
    cudaGetSymbolAddress((void**)&bufA, g_bufA);
    cudaGetSymbolAddress((void**)&bufB, g_bufB);
    cudaGetSymbolAddress((void**)&wpair, g_wpair);

    auto grid = [](int total) { return (total + 255) / 256; };

    wtrans_all_kernel<<<(WT_TOTAL + 255) / 256, 256>>>(c1w, c2w, c3w, ow, dw);

    const int CBLK = BATCH * DD * (HH / 4);   // 784

    // layer 1: conv(1->32)+relu, stats fused (BN0 applied in conv2 staging)
    conv_cl_kernel<1, 32, 4, 128, true, false, -1, true><<<CBLK, 128>>>(x, wpair + W1_OFF, c1b, bufA);
    bn_fin_kernel<<<32, 256>>>(g1, b1, 0, CBLK, 4, 32);

    // layer 2: conv(32->64)+relu (applies BN0), stats fused
    conv_cl_kernel<32, 64, 2, 128, true, false, 0, true><<<CBLK, 128>>>(bufA, wpair + W2_OFF, c2b, bufB);
    bn_fin_kernel<<<64, 256>>>(g2, b2, 1, CBLK, 2, 64);

    // layer 3: conv(64->128)+relu (applies BN1), stats fused, explicit BN2 apply
    conv_cl_kernel<64, 128, 1, 128, true, false, 1, true><<<CBLK, 128>>>(bufB, wpair + W3_OFF, c3b, bufA);
    bn_fin_kernel<<<128, 256>>>(g3, b3, 2, CBLK, 1, 128);
    bn_apply_kernel<<<grid(NSP*128), 256>>>(bufA, 2, 128);

    // offsets conv (128->81), input already BN'd, NCDHW into output buffer (96 threads)
    conv_cl_kernel<128, 81, 1, 96, false, true, -1, false><<<CBLK, 96>>>(bufA, wpair + W4_OFF, ob, offsets);

    // deformable conv (128->128) + relu: ONLY per-block channel sums (no tensor output)
    deform_kernel<<<NSP / 32, 128>>>(bufA, offsets, wpair + W5_OFF, db);
    bn_fin_kernel<<<128, 256>>>(g4, b4, 3, NSP / 32, 1, 128);

    // pool from partials (+BN4 affine) + fc + log_softmax
    head_kernel<<<BATCH, 128>>>(fcw, fcb, out);
}

// round 15
// speedup vs baseline: 1.2349x; 1.1012x over previous
#include <cuda_runtime.h>
#include <math.h>

// ---------------- problem constants ----------------
#define BATCH 4
#define DD 28
#define HH 28
#define WW 8
#define SP (DD*HH*WW)        // 6272
#define NSP (BATCH*SP)       // 25088 = 196*128
#define CMAX 128

typedef unsigned long long ull;

// ---------------- packed f32x2 helpers ----------------
__device__ __forceinline__ ull pk(float a, float b) {
    ull r; asm("mov.b64 %0,{%1,%2};" : "=l"(r) : "f"(a), "f"(b)); return r;
}
__device__ __forceinline__ void upk(ull v, float& a, float& b) {
    asm("mov.b64 {%0,%1},%2;" : "=f"(a), "=f"(b) : "l"(v));
}
__device__ __forceinline__ ull ff2(ull a, ull b, ull c) {
    ull d; asm("fma.rn.f32x2 %0,%1,%2,%3;" : "=l"(d) : "l"(a), "l"(b), "l"(c)); return d;
}

// ---------------- scratch (static device, no allocs) ----------------
__device__ float g_bufA[BATCH*SP*CMAX];   // activations channel-last [b][sp][c]
__device__ float g_bufB[BATCH*SP*CMAX];
__device__ float2 g_wpair[1000000];       // all transposed weights, duplicated pairs
__device__ float g_ps[784*CMAX];          // BN partial sums (deterministic)
__device__ float g_pq[784*CMAX];
__device__ float2 g_bn[4][CMAX];          // per-layer (scale, shift)

// weight region offsets (in float2 elements)
#define W1_OFF 0                         // 27*1*32   = 864
#define W2_OFF 864                       // 27*32*64  = 55296
#define W3_OFF 56160                     // 27*64*128 = 221184
#define W4_OFF 277344                    // 27*128*81 = 279936
#define W5_OFF 557280                    // 27*128*128= 442368  (end 999648)

#define S1 864
#define S2 55296
#define S3 221184
#define S4 279936
#define S5 442368
#define WT_TOTAL (S1+S2+S3+S4+S5)

// ---------------- merged weight transpose: (O,CIN,27) -> pairs [n][ci][o] ----------------
__global__ void wtrans_all_kernel(const float* __restrict__ w1, const float* __restrict__ w2,
                                  const float* __restrict__ w3, const float* __restrict__ w4,
                                  const float* __restrict__ w5) {
    int idx = blockIdx.x * blockDim.x + threadIdx.x;
    if (idx >= WT_TOTAL) return;
    const float* src; float2* dst; int CIN, COUT; int l = idx;
    if (l < S1)              { src = w1; dst = g_wpair + W1_OFF; CIN = 1;   COUT = 32; }
    else if ((l -= S1) < S2) { src = w2; dst = g_wpair + W2_OFF; CIN = 32;  COUT = 64; }
    else if ((l -= S2) < S3) { src = w3; dst = g_wpair + W3_OFF; CIN = 64;  COUT = 128; }
    else if ((l -= S3) < S4) { src = w4; dst = g_wpair + W4_OFF; CIN = 128; COUT = 81; }
    else { l -= S4; src = w5; dst = g_wpair + W5_OFF; CIN = 128; COUT = 128; }
    int n = l % 27;
    int c = (l / 27) % CIN;
    int o = l / (27 * CIN);
    float v = src[l];
    dst[((size_t)n * CIN + c) * COUT + o] = make_float2(v, v);
}

// ---------------- tiled conv3d, channel-last, f32x2 inner, hoisted weights ----------------
// BLOCKT threads, tile: 4h x 8w at fixed d. grid = B*D*(H/4) = 784
template<int CIN, int COUT, int GROUPS, int BLOCKT, bool RELU, bool NCDHW_OUT, int BN_LAYER, bool STATS>
__global__ void conv_cl_kernel(const float* __restrict__ x, const float2* __restrict__ wp,
                               const float* __restrict__ bias, float* __restrict__ y) {
    constexpr int CH = (CIN < 16) ? CIN : 16;
    constexpr int NCH = CIN / CH;
    constexpr int PH = 4 / GROUPS;           // h-rows per thread
    __shared__ float xs[CH][18][12];   // [ci][zd*6+zh][zw padded 10->12]

    int tid = threadIdx.x;
    int blk = blockIdx.x;
    int hb = blk % 7;
    int d  = (blk / 7) % DD;
    int b  = blk / (7 * DD);
    int h0 = hb * 4;
    int grp = tid / COUT;
    if (grp > GROUPS - 1) grp = GROUPS - 1;
    int o = tid - grp * COUT;
    if (o >= COUT) o = 0;

    ull acc2[PH][4];
    #pragma unroll
    for (int ph = 0; ph < PH; ph++)
        #pragma unroll
        for (int j = 0; j < 4; j++) acc2[ph][j] = 0ull;

    for (int cc = 0; cc < NCH; cc++) {
        __syncthreads();
        // stage input tile (zero-padded halo), coalesced over ci
        for (int i = tid; i < 180 * CH; i += BLOCKT) {
            int ci, pos;
            if (CH == 16) { ci = i & 15; pos = i >> 4; }
            else          { ci = i % CH; pos = i / CH; }
            int zw = pos % 10;
            int zh = (pos / 10) % 6;
            int zd = pos / 60;
            int gd = d + zd - 1, gh = h0 + zh - 1, gw = zw - 1;
            float v = 0.0f;
            int cg = cc * CH + ci;
            if ((unsigned)gd < DD && (unsigned)gh < HH && (unsigned)gw < WW) {
                v = x[((size_t)((b * DD + gd) * HH + gh) * WW + gw) * CIN + cg];
                if (BN_LAYER >= 0) { float2 t = g_bn[BN_LAYER][cg]; v = fmaf(v, t.x, t.y); }
            }
            xs[ci][zd * 6 + zh][zw] = v;
        }
        __syncthreads();

        for (int ci = 0; ci < CH; ci++) {
            int cglob = cc * CH + ci;
            #pragma unroll
            for (int zd = 0; zd < 3; zd++) {
                // hoist the 9 taps of this zd-plane into registers (one LDG each)
                ull wreg[9];
                #pragma unroll
                for (int t = 0; t < 9; t++)
                    wreg[t] = *(const ull*)&wp[((size_t)(zd * 9 + t) * CIN + cglob) * COUT + o];
                #pragma unroll
                for (int zl = 0; zl < PH + 2; zl++) {
                    const float2* row = (const float2*)&xs[ci][zd * 6 + grp * PH + zl][0];
                    float2 e0 = row[0], e1 = row[1], e2 = row[2], e3 = row[3], e4 = row[4];
                    ull P[9];
                    P[0] = pk(e0.x, e0.y); P[2] = pk(e1.x, e1.y); P[4] = pk(e2.x, e2.y);
                    P[6] = pk(e3.x, e3.y); P[8] = pk(e4.x, e4.y);
                    P[1] = pk(e0.y, e1.x); P[3] = pk(e1.y, e2.x);
                    P[5] = pk(e2.y, e3.x); P[7] = pk(e3.y, e4.x);
                    #pragma unroll
                    for (int ph = 0; ph < PH; ph++) {
                        int kh1 = zl - ph;               // kh+1
                        if (kh1 < 0 || kh1 > 2) continue; // constant-folds
                        #pragma unroll
                        for (int kw1 = 0; kw1 < 3; kw1++) {
                            ull wv2 = wreg[kh1 * 3 + kw1];
                            #pragma unroll
                            for (int j = 0; j < 4; j++)
                                acc2[ph][j] = ff2(wv2, P[kw1 + 2 * j], acc2[ph][j]);
                        }
                    }
                }
            }
        }
    }

    if (tid < GROUPS * COUT) {
        float bs = bias[o];
        float ssum = 0.f, sq = 0.f;
        #pragma unroll
        for (int ph = 0; ph < PH; ph++) {
            int h = h0 + grp * PH + ph;
            #pragma unroll
            for (int j = 0; j < 4; j++) {
                float v0, v1; upk(acc2[ph][j], v0, v1);
                v0 += bs; v1 += bs;
                if (RELU) { v0 = fmaxf(v0, 0.f); v1 = fmaxf(v1, 0.f); }
                if (STATS) { ssum += v0 + v1; sq += v0 * v0 + v1 * v1; }
                int pw = 2 * j;
                if (NCDHW_OUT) {
                    size_t base = (size_t)(b * COUT + o) * SP + (size_t)(d * HH + h) * WW;
                    y[base + pw] = v0; y[base + pw + 1] = v1;
                } else {
                    size_t base = ((size_t)((b * DD + d) * HH + h) * WW + pw) * COUT + o;
                    y[base] = v0; y[base + COUT] = v1;
                }
            }
        }
        if (STATS) { g_ps[blk * CMAX + tid] = ssum; g_pq[blk * CMAX + tid] = sq; }
    }
}

// ---------------- BN finalize: reduce per-block partials -> (scale, shift) ----------------
__global__ void bn_fin_kernel(const float* __restrict__ gma, const float* __restrict__ bta,
                              int layer, int nblk, int groups, int C) {
    int c = blockIdx.x;
    int t = threadIdx.x;
    __shared__ float sh0[256], sh1[256];
    float s = 0.f, q = 0.f;
    for (int i = t; i < nblk; i += 256) {
        for (int g = 0; g < groups; g++) {
            s += g_ps[i * CMAX + g * C + c];
            q += g_pq[i * CMAX + g * C + c];
        }
    }
    sh0[t] = s; sh1[t] = q;
    __syncthreads();
    for (int st = 128; st > 0; st >>= 1) {
        if (t < st) { sh0[t] += sh0[t + st]; sh1[t] += sh1[t + st]; }
        __syncthreads();
    }
    if (t == 0) {
        float m = sh0[0] / (float)NSP;
        float var = sh1[0] / (float)NSP - m * m;
        float r = rsqrtf(var + 1e-5f);
        float sc = r * gma[c];
        g_bn[layer][c] = make_float2(sc, bta[c] - m * sc);
    }
}

// ---------------- deformable conv: channel-pair sampler with fused BN2, no tensor output ----------------
// Input ht is the RAW conv3 output; BN2 is applied analytically inside the sampler:
//   sample = sc * sum_valid(g*x) + sh * sum_valid(g)     (reference pads AFTER BN -> border 0)
__global__ void deform_kernel(const float* __restrict__ ht,   // channel-last conv3 out [pos][128]
                              const float* __restrict__ off,  // (B,81,D,H,W) NCDHW
                              const float2* __restrict__ wp,  // [n][c][o] duplicated pairs
                              const float* __restrict__ db) {
    __shared__ float s_tile[128 * 36];     // [c][p], row stride 36 floats (144B, 16B-aligned)
    __shared__ int   s_qd[32], s_qh[32], s_qw[32];
    __shared__ float s_td[32], s_th[32], s_tw[32];
    __shared__ float s_ws[32];             // sum of valid corner weights per position

    int tid = threadIdx.x;
    int cp   = tid & 63;       // channel pair index: channels (2cp, 2cp+1)
    int half = tid >> 6;       // which 16 of the 32 positions (sampling phase)
    int posBase = blockIdx.x * 32;

    // BN2 (scale, shift) for this thread's channel pair
    float2 bnc0 = g_bn[2][2 * cp];
    float2 bnc1 = g_bn[2][2 * cp + 1];
    ull scp = pk(bnc0.x, bnc1.x);
    ull shp = pk(bnc0.y, bnc1.y);

    ull acc2[16];
    #pragma unroll
    for (int j = 0; j < 16; j++) acc2[j] = 0ull;

    for (int n = 0; n < 27; n++) {
        int kd = n / 9 - 1, kh = (n / 3) % 3 - 1, kw = n % 3 - 1;
        __syncthreads();
        if (tid < 32) {
            int s = posBase + tid;
            int w = s & 7;
            int t = s >> 3;
            int h = t % HH; t /= HH;
            int d = t % DD;
            int b = t / DD;
            size_t obase = (size_t)b * 81 * SP + (size_t)((d * HH + h) * WW + w);
            float od  = off[obase + (size_t)n * SP];
            float oh  = off[obase + (size_t)(27 + n) * SP];
            float ow_ = off[obase + (size_t)(54 + n) * SP];
            float pd = fminf(fmaxf((float)(d + 1 + kd) + od, 0.f), 29.f);
            float ph = fminf(fmaxf((float)(h + 1 + kh) + oh, 0.f), 29.f);
            float pw = fminf(fmaxf((float)(w + 1 + kw) + ow_, 0.f), 9.f);
            float fd = fminf(fmaxf(floorf(pd), 0.f), 28.f);
            float fh = fminf(fmaxf(floorf(ph), 0.f), 28.f);
            float fw = fminf(fmaxf(floorf(pw), 0.f), 8.f);
            int qd = (int)fd; float td = fminf(fmaxf(pd - fd, 0.f), 1.f);
            int qh = (int)fh; float th = fminf(fmaxf(ph - fh, 0.f), 1.f);
            int qw = (int)fw; float tw = fminf(fmaxf(pw - fw, 0.f), 1.f);
            s_qd[tid] = qd; s_td[tid] = td;
            s_qh[tid] = qh; s_th[tid] = th;
            s_qw[tid] = qw; s_tw[tid] = tw;
            // sum of valid corner weights (for BN shift through zero padding)
            float wsum = 0.f;
            #pragma unroll
            for (int i = 0; i < 2; i++) {
                int zd = qd + i - 1; if ((unsigned)zd >= DD) continue;
                float gd = i ? td : (1.f - td);
                #pragma unroll
                for (int j = 0; j < 2; j++) {
                    int zh = qh + j - 1; if ((unsigned)zh >= HH) continue;
                    float gdh = gd * (j ? th : (1.f - th));
                    #pragma unroll
                    for (int k = 0; k < 2; k++) {
                        int zw = qw + k - 1; if ((unsigned)zw >= WW) continue;
                        wsum += gdh * (k ? tw : (1.f - tw));
                    }
                }
            }
            s_ws[tid] = wsum;
        }
        __syncthreads();

        // sampling: thread = (channel-pair, position-half); 16 positions, f32x2 loads
        for (int pl = 0; pl < 16; pl++) {
            int p = half * 16 + pl;
            int s = posBase + p;
            int b = s / SP;
            int qd = s_qd[p], qh = s_qh[p], qw = s_qw[p];
            float td = s_td[p], th = s_th[p], tw = s_tw[p];
            ull vacc = 0ull;
            #pragma unroll
            for (int i = 0; i < 2; i++) {
                int zd = qd + i - 1;
                if ((unsigned)zd >= DD) continue;
                float gd = i ? td : (1.f - td);
                #pragma unroll
                for (int j = 0; j < 2; j++) {
                    int zh = qh + j - 1;
                    if ((unsigned)zh >= HH) continue;
                    float gdh = gd * (j ? th : (1.f - th));
                    #pragma unroll
                    for (int k = 0; k < 2; k++) {
                        int zw = qw + k - 1;
                        if ((unsigned)zw >= WW) continue;
                        float g = gdh * (k ? tw : (1.f - tw));
                        size_t base = (size_t)((b * DD + zd) * HH + zh) * WW + zw;
                        ull x2 = *(const ull*)&ht[base * CMAX + 2 * cp];
                        vacc = ff2(pk(g, g), x2, vacc);
                    }
                }
            }
            // fold BN2: v = sc*vacc + sh*wsum
            ull ws2 = pk(s_ws[p], s_ws[p]);
            vacc = ff2(scp, vacc, ff2(shp, ws2, 0ull));
            float v0, v1; upk(vacc, v0, v1);
            s_tile[(2 * cp) * 36 + p]     = v0;
            s_tile[(2 * cp + 1) * 36 + p] = v1;
        }
        __syncthreads();

        // GEMV: thread = output channel; 128-bit broadcast smem reads (unchanged)
        const float2* wrow = wp + (size_t)n * 128 * 128;
        for (int c = 0; c < 128; c++) {
            ull wv2 = *(const ull*)&wrow[c * 128 + tid];
            const ulonglong2* st2 = (const ulonglong2*)(s_tile + c * 36);
            #pragma unroll
            for (int k = 0; k < 8; k++) {
                ulonglong2 q = st2[k];
                acc2[2 * k]     = ff2(wv2, q.x, acc2[2 * k]);
                acc2[2 * k + 1] = ff2(wv2, q.y, acc2[2 * k + 1]);
            }
        }
    }

    float bs = db[tid];
    float ssum = 0.f, sq = 0.f;
    #pragma unroll
    for (int j = 0; j < 16; j++) {
        float v0, v1; upk(acc2[j], v0, v1);
        v0 = fmaxf(v0 + bs, 0.f); v1 = fmaxf(v1 + bs, 0.f);
        ssum += v0 + v1; sq += v0 * v0 + v1 * v1;
    }
    g_ps[blockIdx.x * CMAX + tid] = ssum;
    g_pq[blockIdx.x * CMAX + tid] = sq;
}

// ---------------- head: pool from deform per-block partials (+BN4) + FC + log_softmax ----------------
__global__ void head_kernel(const float* __restrict__ fcw, const float* __restrict__ fcb,
                            float* __restrict__ out) {
    int b = blockIdx.x;
    int c = threadIdx.x;   // 128
    float s = 0.f;
    const float* pp = g_ps + (size_t)(b * 196) * CMAX + c;
    for (int i = 0; i < 196; i++) s += pp[(size_t)i * CMAX];
    __shared__ float pooled[128];
    __shared__ float logits[10];
    float2 bn = g_bn[3][c];
    pooled[c] = fmaf(s / (float)SP, bn.x, bn.y);
    __syncthreads();
    if (c < 10) {
        float l = fcb[c];
        for (int k = 0; k < 128; k++) l += pooled[k] * fcw[c * 128 + k];
        logits[c] = l;
    }
    __syncthreads();
    if (c == 0) {
        float mx = logits[0];
        for (int j = 1; j < 10; j++) mx = fmaxf(mx, logits[j]);
        float se = 0.f;
        for (int j = 0; j < 10; j++) se += expf(logits[j] - mx);
        float lse = mx + logf(se);
        for (int j = 0; j < 10; j++) out[b * 10 + j] = logits[j] - lse;
    }
}

// ---------------- launcher ----------------
extern "C" void kernel_launch(void* const* d_in, const int* in_sizes, int n_in,
                              void* d_out, int out_size) {
    const float* x   = (const float*)d_in[0];
    const float* c1w = (const float*)d_in[1];  const float* c1b = (const float*)d_in[2];
    const float* g1  = (const float*)d_in[3];  const float* b1  = (const float*)d_in[4];
    const float* c2w = (const float*)d_in[5];  const float* c2b = (const float*)d_in[6];
    const float* g2  = (const float*)d_in[7];  const float* b2  = (const float*)d_in[8];
    const float* c3w = (const float*)d_in[9];  const float* c3b = (const float*)d_in[10];
    const float* g3  = (const float*)d_in[11]; const float* b3  = (const float*)d_in[12];
    const float* ow  = (const float*)d_in[13]; const float* ob  = (const float*)d_in[14];
    const float* dw  = (const float*)d_in[15]; const float* db  = (const float*)d_in[16];
    const float* g4  = (const float*)d_in[17]; const float* b4  = (const float*)d_in[18];
    const float* fcw = (const float*)d_in[19]; const float* fcb = (const float*)d_in[20];

    float* out = (float*)d_out;
    float* offsets = out + BATCH * 10;   // logits first, then offsets (NCDHW)

    float *bufA, *bufB; float2* wpair;
    cudaGetSymbolAddress((void**)&bufA, g_bufA);
    cudaGetSymbolAddress((void**)&bufB, g_bufB);
    cudaGetSymbolAddress((void**)&wpair, g_wpair);

    wtrans_all_kernel<<<(WT_TOTAL + 255) / 256, 256>>>(c1w, c2w, c3w, ow, dw);

    const int CBLK = BATCH * DD * (HH / 4);   // 784

    // layer 1: conv(1->32)+relu, stats fused (BN0 applied in conv2 staging)
    conv_cl_kernel<1, 32, 4, 128, true, false, -1, true><<<CBLK, 128>>>(x, wpair + W1_OFF, c1b, bufA);
    bn_fin_kernel<<<32, 256>>>(g1, b1, 0, CBLK, 4, 32);

    // layer 2: conv(32->64)+relu (applies BN0), stats fused
    conv_cl_kernel<32, 64, 2, 128, true, false, 0, true><<<CBLK, 128>>>(bufA, wpair + W2_OFF, c2b, bufB);
    bn_fin_kernel<<<64, 256>>>(g2, b2, 1, CBLK, 2, 64);

    // layer 3: conv(64->128)+relu (applies BN1), stats fused; output left RAW (BN2 folded downstream)
    conv_cl_kernel<64, 128, 1, 128, true, false, 1, true><<<CBLK, 128>>>(bufB, wpair + W3_OFF, c3b, bufA);
    bn_fin_kernel<<<128, 256>>>(g3, b3, 2, CBLK, 1, 128);

    // offsets conv (128->81): applies BN2 at staging, NCDHW into output buffer (96 threads)
    conv_cl_kernel<128, 81, 1, 96, false, true, 2, false><<<CBLK, 96>>>(bufA, wpair + W4_OFF, ob, offsets);

    // deformable conv (128->128) + relu: BN2 folded into sampler, only per-block channel sums
    deform_kernel<<<NSP / 32, 128>>>(bufA, offsets, wpair + W5_OFF, db);
    bn_fin_kernel<<<128, 256>>>(g4, b4, 3, NSP / 32, 1, 128);

    // pool from partials (+BN4 affine) + fc + log_softmax
    head_kernel<<<BATCH, 128>>>(fcw, fcb, out);
}

// round 16
// speedup vs baseline: 1.2748x; 1.0323x over previous
#include <cuda_runtime.h>
#include <math.h>

// ---------------- problem constants ----------------
#define BATCH 4
#define DD 28
#define HH 28
#define WW 8
#define SP (DD*HH*WW)        // 6272
#define NSP (BATCH*SP)       // 25088 = 196*128
#define CMAX 128

typedef unsigned long long ull;

// ---------------- packed f32x2 helpers ----------------
__device__ __forceinline__ ull pk(float a, float b) {
    ull r; asm("mov.b64 %0,{%1,%2};" : "=l"(r) : "f"(a), "f"(b)); return r;
}
__device__ __forceinline__ void upk(ull v, float& a, float& b) {
    asm("mov.b64 {%0,%1},%2;" : "=f"(a), "=f"(b) : "l"(v));
}
__device__ __forceinline__ ull ff2(ull a, ull b, ull c) {
    ull d; asm("fma.rn.f32x2 %0,%1,%2,%3;" : "=l"(d) : "l"(a), "l"(b), "l"(c)); return d;
}

// ---------------- scratch (static device, no allocs) ----------------
__device__ float g_bufA[BATCH*SP*CMAX];   // activations channel-last [b][sp][c]
__device__ float g_bufB[BATCH*SP*CMAX];
__device__ float2 g_wpair[557280];        // conv weights, duplicated pairs
__device__ float  g_wdef[27*128*128];     // deform weights, PLAIN [n][c][o] (half the L2 bytes)
__device__ float g_ps[784*CMAX];          // BN partial sums (deterministic)
__device__ float g_pq[784*CMAX];
__device__ float2 g_bn[4][CMAX];          // per-layer (scale, shift)

// weight region offsets (in float2 elements)
#define W1_OFF 0                         // 27*1*32   = 864
#define W2_OFF 864                       // 27*32*64  = 55296
#define W3_OFF 56160                     // 27*64*128 = 221184
#define W4_OFF 277344                    // 27*128*81 = 279936 (end 557280)

#define S1 864
#define S2 55296
#define S3 221184
#define S4 279936
#define S5 442368
#define WT_TOTAL (S1+S2+S3+S4+S5)

// ---------------- merged weight transpose ----------------
__global__ void wtrans_all_kernel(const float* __restrict__ w1, const float* __restrict__ w2,
                                  const float* __restrict__ w3, const float* __restrict__ w4,
                                  const float* __restrict__ w5) {
    int idx = blockIdx.x * blockDim.x + threadIdx.x;
    if (idx >= WT_TOTAL) return;
    const float* src; float2* dst; int CIN, COUT; int l = idx; int plain = 0;
    if (l < S1)              { src = w1; dst = g_wpair + W1_OFF; CIN = 1;   COUT = 32; }
    else if ((l -= S1) < S2) { src = w2; dst = g_wpair + W2_OFF; CIN = 32;  COUT = 64; }
    else if ((l -= S2) < S3) { src = w3; dst = g_wpair + W3_OFF; CIN = 64;  COUT = 128; }
    else if ((l -= S3) < S4) { src = w4; dst = g_wpair + W4_OFF; CIN = 128; COUT = 81; }
    else { l -= S4; src = w5; dst = nullptr; CIN = 128; COUT = 128; plain = 1; }
    int n = l % 27;
    int c = (l / 27) % CIN;
    int o = l / (27 * CIN);
    float v = src[l];
    if (plain) g_wdef[((size_t)n * 128 + c) * 128 + o] = v;
    else       dst[((size_t)n * CIN + c) * COUT + o] = make_float2(v, v);
}

// ---------------- tiled conv3d, channel-last, f32x2 inner, hoisted weights ----------------
// BLOCKT threads, tile: 4h x 8w at fixed d. grid = B*D*(H/4) = 784
template<int CIN, int COUT, int GROUPS, int BLOCKT, bool RELU, bool NCDHW_OUT, int BN_LAYER, bool STATS>
__global__ void conv_cl_kernel(const float* __restrict__ x, const float2* __restrict__ wp,
                               const float* __restrict__ bias, float* __restrict__ y) {
    constexpr int CH = (CIN < 16) ? CIN : 16;
    constexpr int NCH = CIN / CH;
    constexpr int PH = 4 / GROUPS;           // h-rows per thread
    __shared__ float xs[CH][18][12];   // [ci][zd*6+zh][zw padded 10->12]

    int tid = threadIdx.x;
    int blk = blockIdx.x;
    int hb = blk % 7;
    int d  = (blk / 7) % DD;
    int b  = blk / (7 * DD);
    int h0 = hb * 4;
    int grp = tid / COUT;
    if (grp > GROUPS - 1) grp = GROUPS - 1;
    int o = tid - grp * COUT;
    if (o >= COUT) o = 0;

    ull acc2[PH][4];
    #pragma unroll
    for (int ph = 0; ph < PH; ph++)
        #pragma unroll
        for (int j = 0; j < 4; j++) acc2[ph][j] = 0ull;

    for (int cc = 0; cc < NCH; cc++) {
        __syncthreads();
        // stage input tile (zero-padded halo), coalesced over ci
        for (int i = tid; i < 180 * CH; i += BLOCKT) {
            int ci, pos;
            if (CH == 16) { ci = i & 15; pos = i >> 4; }
            else          { ci = i % CH; pos = i / CH; }
            int zw = pos % 10;
            int zh = (pos / 10) % 6;
            int zd = pos / 60;
            int gd = d + zd - 1, gh = h0 + zh - 1, gw = zw - 1;
            float v = 0.0f;
            int cg = cc * CH + ci;
            if ((unsigned)gd < DD && (unsigned)gh < HH && (unsigned)gw < WW) {
                v = x[((size_t)((b * DD + gd) * HH + gh) * WW + gw) * CIN + cg];
                if (BN_LAYER >= 0) { float2 t = g_bn[BN_LAYER][cg]; v = fmaf(v, t.x, t.y); }
            }
            xs[ci][zd * 6 + zh][zw] = v;
        }
        __syncthreads();

        for (int ci = 0; ci < CH; ci++) {
            int cglob = cc * CH + ci;
            #pragma unroll
            for (int zd = 0; zd < 3; zd++) {
                // hoist the 9 taps of this zd-plane into registers (one LDG each)
                ull wreg[9];
                #pragma unroll
                for (int t = 0; t < 9; t++)
                    wreg[t] = *(const ull*)&wp[((size_t)(zd * 9 + t) * CIN + cglob) * COUT + o];
                #pragma unroll
                for (int zl = 0; zl < PH + 2; zl++) {
                    const float2* row = (const float2*)&xs[ci][zd * 6 + grp * PH + zl][0];
                    float2 e0 = row[0], e1 = row[1], e2 = row[2], e3 = row[3], e4 = row[4];
                    ull P[9];
                    P[0] = pk(e0.x, e0.y); P[2] = pk(e1.x, e1.y); P[4] = pk(e2.x, e2.y);
                    P[6] = pk(e3.x, e3.y); P[8] = pk(e4.x, e4.y);
                    P[1] = pk(e0.y, e1.x); P[3] = pk(e1.y, e2.x);
                    P[5] = pk(e2.y, e3.x); P[7] = pk(e3.y, e4.x);
                    #pragma unroll
                    for (int ph = 0; ph < PH; ph++) {
                        int kh1 = zl - ph;               // kh+1
                        if (kh1 < 0 || kh1 > 2) continue; // constant-folds
                        #pragma unroll
                        for (int kw1 = 0; kw1 < 3; kw1++) {
                            ull wv2 = wreg[kh1 * 3 + kw1];
                            #pragma unroll
                            for (int j = 0; j < 4; j++)
                                acc2[ph][j] = ff2(wv2, P[kw1 + 2 * j], acc2[ph][j]);
                        }
                    }
                }
            }
        }
    }

    if (tid < GROUPS * COUT) {
        float bs = bias[o];
        float ssum = 0.f, sq = 0.f;
        #pragma unroll
        for (int ph = 0; ph < PH; ph++) {
            int h = h0 + grp * PH + ph;
            #pragma unroll
            for (int j = 0; j < 4; j++) {
                float v0, v1; upk(acc2[ph][j], v0, v1);
                v0 += bs; v1 += bs;
                if (RELU) { v0 = fmaxf(v0, 0.f); v1 = fmaxf(v1, 0.f); }
                if (STATS) { ssum += v0 + v1; sq += v0 * v0 + v1 * v1; }
                int pw = 2 * j;
                if (NCDHW_OUT) {
                    size_t base = (size_t)(b * COUT + o) * SP + (size_t)(d * HH + h) * WW;
                    y[base + pw] = v0; y[base + pw + 1] = v1;
                } else {
                    size_t base = ((size_t)((b * DD + d) * HH + h) * WW + pw) * COUT + o;
                    y[base] = v0; y[base + COUT] = v1;
                }
            }
        }
        if (STATS) { g_ps[blk * CMAX + tid] = ssum; g_pq[blk * CMAX + tid] = sq; }
    }
}

// ---------------- BN finalize: reduce per-block partials -> (scale, shift) ----------------
__global__ void bn_fin_kernel(const float* __restrict__ gma, const float* __restrict__ bta,
                              int layer, int nblk, int groups, int C) {
    int c = blockIdx.x;
    int t = threadIdx.x;
    __shared__ float sh0[256], sh1[256];
    float s = 0.f, q = 0.f;
    for (int i = t; i < nblk; i += 256) {
        for (int g = 0; g < groups; g++) {
            s += g_ps[i * CMAX + g * C + c];
            q += g_pq[i * CMAX + g * C + c];
        }
    }
    sh0[t] = s; sh1[t] = q;
    __syncthreads();
    for (int st = 128; st > 0; st >>= 1) {
        if (t < st) { sh0[t] += sh0[t + st]; sh1[t] += sh1[t + st]; }
        __syncthreads();
    }
    if (t == 0) {
        float m = sh0[0] / (float)NSP;
        float var = sh1[0] / (float)NSP - m * m;
        float r = rsqrtf(var + 1e-5f);
        float sc = r * gma[c];
        g_bn[layer][c] = make_float2(sc, bta[c] - m * sc);
    }
}

// ---------------- deformable conv: channel-pair sampler + BN2 fold + plain-float GEMV weights ----------------
__global__ void deform_kernel(const float* __restrict__ ht,   // channel-last conv3 out (raw) [pos][128]
                              const float* __restrict__ off,  // (B,81,D,H,W) NCDHW
                              const float* __restrict__ db) {
    __shared__ float s_tile[128 * 36];     // [c][p], row stride 36 floats (144B, 16B-aligned)
    __shared__ int   s_qd[32], s_qh[32], s_qw[32];
    __shared__ float s_td[32], s_th[32], s_tw[32];
    __shared__ float s_ws[32];             // sum of valid corner weights per position

    int tid = threadIdx.x;
    int cp   = tid & 63;       // channel pair index: channels (2cp, 2cp+1)
    int half = tid >> 6;       // which 16 of the 32 positions (sampling phase)
    int posBase = blockIdx.x * 32;

    float2 bnc0 = g_bn[2][2 * cp];
    float2 bnc1 = g_bn[2][2 * cp + 1];
    ull scp = pk(bnc0.x, bnc1.x);
    ull shp = pk(bnc0.y, bnc1.y);

    ull acc2[16];
    #pragma unroll
    for (int j = 0; j < 16; j++) acc2[j] = 0ull;

    for (int n = 0; n < 27; n++) {
        int kd = n / 9 - 1, kh = (n / 3) % 3 - 1, kw = n % 3 - 1;
        __syncthreads();
        if (tid < 32) {
            int s = posBase + tid;
            int w = s & 7;
            int t = s >> 3;
            int h = t % HH; t /= HH;
            int d = t % DD;
            int b = t / DD;
            size_t obase = (size_t)b * 81 * SP + (size_t)((d * HH + h) * WW + w);
            float od  = off[obase + (size_t)n * SP];
            float oh  = off[obase + (size_t)(27 + n) * SP];
            float ow_ = off[obase + (size_t)(54 + n) * SP];
            float pd = fminf(fmaxf((float)(d + 1 + kd) + od, 0.f), 29.f);
            float ph = fminf(fmaxf((float)(h + 1 + kh) + oh, 0.f), 29.f);
            float pw = fminf(fmaxf((float)(w + 1 + kw) + ow_, 0.f), 9.f);
            float fd = fminf(fmaxf(floorf(pd), 0.f), 28.f);
            float fh = fminf(fmaxf(floorf(ph), 0.f), 28.f);
            float fw = fminf(fmaxf(floorf(pw), 0.f), 8.f);
            int qd = (int)fd; float td = fminf(fmaxf(pd - fd, 0.f), 1.f);
            int qh = (int)fh; float th = fminf(fmaxf(ph - fh, 0.f), 1.f);
            int qw = (int)fw; float tw = fminf(fmaxf(pw - fw, 0.f), 1.f);
            s_qd[tid] = qd; s_td[tid] = td;
            s_qh[tid] = qh; s_th[tid] = th;
            s_qw[tid] = qw; s_tw[tid] = tw;
            float wsum = 0.f;
            #pragma unroll
            for (int i = 0; i < 2; i++) {
                int zd = qd + i - 1; if ((unsigned)zd >= DD) continue;
                float gd = i ? td : (1.f - td);
                #pragma unroll
                for (int j = 0; j < 2; j++) {
                    int zh = qh + j - 1; if ((unsigned)zh >= HH) continue;
                    float gdh = gd * (j ? th : (1.f - th));
                    #pragma unroll
                    for (int k = 0; k < 2; k++) {
                        int zw = qw + k - 1; if ((unsigned)zw >= WW) continue;
                        wsum += gdh * (k ? tw : (1.f - tw));
                    }
                }
            }
            s_ws[tid] = wsum;
        }
        __syncthreads();

        // sampling: thread = (channel-pair, position-half); 16 positions, f32x2 loads
        for (int pl = 0; pl < 16; pl++) {
            int p = half * 16 + pl;
            int s = posBase + p;
            int b = s / SP;
            int qd = s_qd[p], qh = s_qh[p], qw = s_qw[p];
            float td = s_td[p], th = s_th[p], tw = s_tw[p];
            ull vacc = 0ull;
            #pragma unroll
            for (int i = 0; i < 2; i++) {
                int zd = qd + i - 1;
                if ((unsigned)zd >= DD) continue;
                float gd = i ? td : (1.f - td);
                #pragma unroll
                for (int j = 0; j < 2; j++) {
                    int zh = qh + j - 1;
                    if ((unsigned)zh >= HH) continue;
                    float gdh = gd * (j ? th : (1.f - th));
                    #pragma unroll
                    for (int k = 0; k < 2; k++) {
                        int zw = qw + k - 1;
                        if ((unsigned)zw >= WW) continue;
                        float g = gdh * (k ? tw : (1.f - tw));
                        size_t base = (size_t)((b * DD + zd) * HH + zh) * WW + zw;
                        ull x2 = *(const ull*)&ht[base * CMAX + 2 * cp];
                        vacc = ff2(pk(g, g), x2, vacc);
                    }
                }
            }
            ull ws2 = pk(s_ws[p], s_ws[p]);
            vacc = ff2(scp, vacc, ff2(shp, ws2, 0ull));
            float v0, v1; upk(vacc, v0, v1);
            s_tile[(2 * cp) * 36 + p]     = v0;
            s_tile[(2 * cp + 1) * 36 + p] = v1;
        }
        __syncthreads();

        // GEMV: thread = output channel; plain-float weight loads (half the L2 bytes)
        const float* wrow = g_wdef + (size_t)n * 128 * 128;
        for (int c = 0; c < 128; c++) {
            float wv = wrow[c * 128 + tid];
            ull wv2 = pk(wv, wv);
            const ulonglong2* st2 = (const ulonglong2*)(s_tile + c * 36);
            #pragma unroll
            for (int k = 0; k < 8; k++) {
                ulonglong2 q = st2[k];
                acc2[2 * k]     = ff2(wv2, q.x, acc2[2 * k]);
                acc2[2 * k + 1] = ff2(wv2, q.y, acc2[2 * k + 1]);
            }
        }
    }

    float bs = db[tid];
    float ssum = 0.f, sq = 0.f;
    #pragma unroll
    for (int j = 0; j < 16; j++) {
        float v0, v1; upk(acc2[j], v0, v1);
        v0 = fmaxf(v0 + bs, 0.f); v1 = fmaxf(v1 + bs, 0.f);
        ssum += v0 + v1; sq += v0 * v0 + v1 * v1;
    }
    g_ps[blockIdx.x * CMAX + tid] = ssum;
    g_pq[blockIdx.x * CMAX + tid] = sq;
}

// ---------------- head: pool from deform per-block partials (+BN4) + FC + log_softmax ----------------
__global__ void head_kernel(const float* __restrict__ fcw, const float* __restrict__ fcb,
                            float* __restrict__ out) {
    int b = blockIdx.x;
    int c = threadIdx.x;   // 128
    float s = 0.f;
    const float* pp = g_ps + (size_t)(b * 196) * CMAX + c;
    for (int i = 0; i < 196; i++) s += pp[(size_t)i * CMAX];
    __shared__ float pooled[128];
    __shared__ float logits[10];
    float2 bn = g_bn[3][c];
    pooled[c] = fmaf(s / (float)SP, bn.x, bn.y);
    __syncthreads();
    if (c < 10) {
        float l = fcb[c];
        for (int k = 0; k < 128; k++) l += pooled[k] * fcw[c * 128 + k];
        logits[c] = l;
    }
    __syncthreads();
    if (c == 0) {
        float mx = logits[0];
        for (int j = 1; j < 10; j++) mx = fmaxf(mx, logits[j]);
        float se = 0.f;
        for (int j = 0; j < 10; j++) se += expf(logits[j] - mx);
        float lse = mx + logf(se);
        for (int j = 0; j < 10; j++) out[b * 10 + j] = logits[j] - lse;
    }
}

// ---------------- launcher ----------------
extern "C" void kernel_launch(void* const* d_in, const int* in_sizes, int n_in,
                              void* d_out, int out_size) {
    const float* x   = (const float*)d_in[0];
    const float* c1w = (const float*)d_in[1];  const float* c1b = (const float*)d_in[2];
    const float* g1  = (const float*)d_in[3];  const float* b1  = (const float*)d_in[4];
    const float* c2w = (const float*)d_in[5];  const float* c2b = (const float*)d_in[6];
    const float* g2  = (const float*)d_in[7];  const float* b2  = (const float*)d_in[8];
    const float* c3w = (const float*)d_in[9];  const float* c3b = (const float*)d_in[10];
    const float* g3  = (const float*)d_in[11]; const float* b3  = (const float*)d_in[12];
    const float* ow  = (const float*)d_in[13]; const float* ob  = (const float*)d_in[14];
    const float* dw  = (const float*)d_in[15]; const float* db  = (const float*)d_in[16];
    const float* g4  = (const float*)d_in[17]; const float* b4  = (const float*)d_in[18];
    const float* fcw = (const float*)d_in[19]; const float* fcb = (const float*)d_in[20];

    float* out = (float*)d_out;
    float* offsets = out + BATCH * 10;   // logits first, then offsets (NCDHW)

    float *bufA, *bufB; float2* wpair;
    cudaGetSymbolAddress((void**)&bufA, g_bufA);
    cudaGetSymbolAddress((void**)&bufB, g_bufB);
    cudaGetSymbolAddress((void**)&wpair, g_wpair);

    wtrans_all_kernel<<<(WT_TOTAL + 255) / 256, 256>>>(c1w, c2w, c3w, ow, dw);

    const int CBLK = BATCH * DD * (HH / 4);   // 784

    // layer 1: conv(1->32)+relu, stats fused (BN0 applied in conv2 staging)
    conv_cl_kernel<1, 32, 4, 128, true, false, -1, true><<<CBLK, 128>>>(x, wpair + W1_OFF, c1b, bufA);
    bn_fin_kernel<<<32, 256>>>(g1, b1, 0, CBLK, 4, 32);

    // layer 2: conv(32->64)+relu (applies BN0), stats fused
    conv_cl_kernel<32, 64, 2, 128, true, false, 0, true><<<CBLK, 128>>>(bufA, wpair + W2_OFF, c2b, bufB);
    bn_fin_kernel<<<64, 256>>>(g2, b2, 1, CBLK, 2, 64);

    // layer 3: conv(64->128)+relu (applies BN1), stats fused; output left RAW (BN2 folded downstream)
    conv_cl_kernel<64, 128, 1, 128, true, false, 1, true><<<CBLK, 128>>>(bufB, wpair + W3_OFF, c3b, bufA);
    bn_fin_kernel<<<128, 256>>>(g3, b3, 2, CBLK, 1, 128);

    // offsets conv (128->81): applies BN2 at staging, NCDHW into output buffer (96 threads)
    conv_cl_kernel<128, 81, 1, 96, false, true, 2, false><<<CBLK, 96>>>(bufA, wpair + W4_OFF, ob, offsets);

    // deformable conv (128->128) + relu: BN2 in sampler, plain-float GEMV weights, partials only
    deform_kernel<<<NSP / 32, 128>>>(bufA, offsets, db);
    bn_fin_kernel<<<128, 256>>>(g4, b4, 3, NSP / 32, 1, 128);

    // pool from partials (+BN4 affine) + fc + log_softmax
    head_kernel<<<BATCH, 128>>>(fcw, fcb, out);
}